// round 2
// baseline (speedup 1.0000x reference)
#include <cuda_runtime.h>
#include <cstdint>
#include <cstddef>

#define MAXN 30000

__device__ float g_S[(size_t)MAXN * 256];
__device__ float g_P[(size_t)MAXN * 256];
__device__ float g_K[(size_t)MAXN * 256];
__device__ float g_V[(size_t)MAXN * 256];
__device__ float g_U[(size_t)MAXN * 8 * 256];
__device__ float g_A[(size_t)MAXN * 8 * 256];
__device__ int   g_maskMode;  // 0=uint8, 1=int32, 2=float32

// Detect mask dtype from raw bytes (deterministic, data-driven).
__global__ void detect_kernel(const unsigned char* __restrict__ m, int nelem) {
    __shared__ int s_nzoff, s_badf, s_anyf;
    if (threadIdx.x == 0) { s_nzoff = 0; s_badf = 0; s_anyf = 0; }
    __syncthreads();
    int words = min(nelem / 4, 1024);  // nelem is a lower bound on bytes
    const unsigned int* wm = (const unsigned int*)m;
    int nz = 0, bf = 0, af = 0;
    for (int i = threadIdx.x; i < words; i += blockDim.x) {
        unsigned int w = wm[i];
        if (w >> 8) nz = 1;
        if (w != 0u && w != 0x3F800000u) bf = 1;
        if (w == 0x3F800000u) af = 1;
    }
    if (nz) atomicOr(&s_nzoff, 1);
    if (bf) atomicOr(&s_badf, 1);
    if (af) atomicOr(&s_anyf, 1);
    __syncthreads();
    if (threadIdx.x == 0)
        g_maskMode = (!s_badf && s_anyf) ? 2 : (!s_nzoff ? 1 : 0);
}

__device__ __forceinline__ bool mask_at(const void* p, int i, int mode) {
    if (mode == 0) return ((const unsigned char*)p)[i] != 0;
    if (mode == 1) return ((const int*)p)[i] != 0;
    return ((const float*)p)[i] != 0.0f;
}

// C[m,:256] = A[src(m),:256] . B[n,:256], B row-major (i.e. C = A @ B^T).
// BM=128, BN=128, BK=16, 256 thr, 8x8 regs.
__global__ void sgemm_nt(const float* __restrict__ A, long lda,
                         const int* __restrict__ gather,
                         const float* __restrict__ B,
                         float* __restrict__ C, int M) {
    __shared__ float As[16][132];
    __shared__ float Bs[16][132];
    const int t = threadIdx.x;
    const int m0 = blockIdx.x * 128, n0 = blockIdx.y * 128;
    const int tx = t & 15, ty = t >> 4;
    const int lrow = t >> 1, lcol = (t & 1) * 8;
    const int gm = m0 + lrow;
    const bool mok = (gm < M);
    int src = mok ? (gather ? gather[gm] : gm) : 0;
    const float* Ap = A + (size_t)src * lda + lcol;
    const float* Bp = B + (size_t)(n0 + lrow) * 256 + lcol;
    float acc[8][8];
#pragma unroll
    for (int i = 0; i < 8; i++)
#pragma unroll
        for (int j = 0; j < 8; j++) acc[i][j] = 0.f;
    for (int k0 = 0; k0 < 256; k0 += 16) {
        float4 a0 = make_float4(0,0,0,0), a1 = a0;
        if (mok) { a0 = *(const float4*)(Ap + k0); a1 = *(const float4*)(Ap + k0 + 4); }
        float4 b0 = *(const float4*)(Bp + k0), b1 = *(const float4*)(Bp + k0 + 4);
        As[lcol+0][lrow]=a0.x; As[lcol+1][lrow]=a0.y; As[lcol+2][lrow]=a0.z; As[lcol+3][lrow]=a0.w;
        As[lcol+4][lrow]=a1.x; As[lcol+5][lrow]=a1.y; As[lcol+6][lrow]=a1.z; As[lcol+7][lrow]=a1.w;
        Bs[lcol+0][lrow]=b0.x; Bs[lcol+1][lrow]=b0.y; Bs[lcol+2][lrow]=b0.z; Bs[lcol+3][lrow]=b0.w;
        Bs[lcol+4][lrow]=b1.x; Bs[lcol+5][lrow]=b1.y; Bs[lcol+6][lrow]=b1.z; Bs[lcol+7][lrow]=b1.w;
        __syncthreads();
#pragma unroll
        for (int kk = 0; kk < 16; kk++) {
            float a[8], b[8];
            *(float4*)(a)   = *(const float4*)&As[kk][ty*8];
            *(float4*)(a+4) = *(const float4*)&As[kk][ty*8+4];
            *(float4*)(b)   = *(const float4*)&Bs[kk][tx*8];
            *(float4*)(b+4) = *(const float4*)&Bs[kk][tx*8+4];
#pragma unroll
            for (int i = 0; i < 8; i++)
#pragma unroll
                for (int j = 0; j < 8; j++) acc[i][j] += a[i] * b[j];
        }
        __syncthreads();
    }
#pragma unroll
    for (int i = 0; i < 8; i++) {
        int m = m0 + ty * 8 + i;
        if (m < M) {
            float4* cp = (float4*)(C + (size_t)m * 256 + n0 + tx * 8);
            cp[0] = make_float4(acc[i][0], acc[i][1], acc[i][2], acc[i][3]);
            cp[1] = make_float4(acc[i][4], acc[i][5], acc[i][6], acc[i][7]);
        }
    }
}

// u[n,h,d] = sum_{j<32} K[n,h*32+j] * Wq[h*32+j,d]
__global__ void u_kernel(const float* __restrict__ Wq, int N) {
    __shared__ float Wqs[32][256];
    __shared__ float kvs[64][33];
    const int h = blockIdx.y, n0 = blockIdx.x * 64, t = threadIdx.x;
#pragma unroll
    for (int i = 0; i < 32; i++) Wqs[i][t] = Wq[(size_t)(h*32+i)*256 + t];
#pragma unroll
    for (int i = 0; i < 8; i++) {
        int node = i * 8 + (t >> 5), j = t & 31, n = n0 + node;
        kvs[node][j] = (n < N) ? g_K[(size_t)n*256 + h*32 + j] : 0.f;
    }
    __syncthreads();
    const int txd = (t & 63) * 4, ng = (t >> 6) * 4;
    for (int p = 0; p < 4; p++) {
        const int nb = p * 16 + ng;
        float acc[4][4];
#pragma unroll
        for (int c = 0; c < 4; c++)
#pragma unroll
            for (int e = 0; e < 4; e++) acc[c][e] = 0.f;
#pragma unroll
        for (int j = 0; j < 32; j++) {
            float4 wq = *(const float4*)&Wqs[j][txd];
#pragma unroll
            for (int c = 0; c < 4; c++) {
                float kv = kvs[nb+c][j];
                acc[c][0] += kv*wq.x; acc[c][1] += kv*wq.y;
                acc[c][2] += kv*wq.z; acc[c][3] += kv*wq.w;
            }
        }
#pragma unroll
        for (int c = 0; c < 4; c++) {
            int n = n0 + nb + c;
            if (n < N)
                *(float4*)&g_U[((size_t)n*8 + h)*256 + txd] =
                    make_float4(acc[c][0], acc[c][1], acc[c][2], acc[c][3]);
        }
    }
}

// scores + masked softmax + aggregate. 4 nodes/block, warp w = head w.
__global__ void attn_kernel(const float* __restrict__ ccw, const float* __restrict__ cw,
                            const void* __restrict__ ccwm, const void* __restrict__ cwm,
                            int N) {
    __shared__ float msg_s[18][257];
    __shared__ float u_s[8][257];
    __shared__ float sc_s[8][32];
    __shared__ float p_s[8][18];
    const int t = threadIdx.x, lane = t & 31, w = t >> 5;
    const int mode = g_maskMode;
    const float NEG = __int_as_float(0xff800000);
    for (int nl = 0; nl < 4; nl++) {
        const int n = blockIdx.x * 4 + nl;
        if (n >= N) return;
        const size_t nb = n;
#pragma unroll
        for (int i = 0; i < 8; i++) u_s[i][t] = g_U[nb*2048 + i*256 + t];
#pragma unroll
        for (int s = 0; s < 18; s++) {
            float v;
            if (s < 8)       v = ccw[nb*2048 + s*256 + t];
            else if (s == 8) v = g_S[nb*256 + t];
            else if (s == 9) v = g_P[nb*256 + t];
            else             v = cw[nb*2048 + (size_t)(s-10)*256 + t];
            msg_s[s][t] = v;
        }
        __syncthreads();
        for (int s = 0; s < 18; s++) {
            float part = 0.f;
#pragma unroll
            for (int i = 0; i < 256; i += 32)
                part += msg_s[s][lane+i] * u_s[w][lane+i];
#pragma unroll
            for (int off = 16; off; off >>= 1)
                part += __shfl_xor_sync(0xFFFFFFFFu, part, off);
            if (lane == 0) sc_s[w][s] = part;
        }
        __syncwarp();
        {
            bool valid = false; float v = NEG;
            if (lane < 18) {
                if (lane < 8)       valid = mask_at(ccwm, n*8 + lane, mode);
                else if (lane < 10) valid = true;
                else                valid = mask_at(cwm, n*8 + lane - 10, mode);
                if (valid) v = sc_s[w][lane] * 0.17677669529663688f;
            }
            float mx = v;
#pragma unroll
            for (int off = 16; off; off >>= 1)
                mx = fmaxf(mx, __shfl_xor_sync(0xFFFFFFFFu, mx, off));
            float e = valid ? expf(v - mx) : 0.f;
            float sm = e;
#pragma unroll
            for (int off = 16; off; off >>= 1)
                sm += __shfl_xor_sync(0xFFFFFFFFu, sm, off);
            if (lane < 18) p_s[w][lane] = e / sm;
        }
        __syncthreads();
        float acc[8];
#pragma unroll
        for (int h = 0; h < 8; h++) acc[h] = 0.f;
#pragma unroll
        for (int s = 0; s < 18; s++) {
            float m = msg_s[s][t];
#pragma unroll
            for (int h = 0; h < 8; h++) acc[h] += p_s[h][s] * m;
        }
#pragma unroll
        for (int h = 0; h < 8; h++) g_A[(nb*8 + h)*256 + t] = acc[h];
        __syncthreads();
    }
}

// V[n,h*32+d'] = sum_d Wv[h*32+d',d] * agg[n,h,d]. BM=128,BN=32,BK=16.
__global__ void vproj_kernel(const float* __restrict__ Wv, int M) {
    __shared__ float As[16][132];
    __shared__ float Bs[16][36];
    const int h = blockIdx.y, m0 = blockIdx.x * 128, t = threadIdx.x;
    const int tx = t & 7, ty = t >> 3;
    const int lrow = t >> 1, lcol = (t & 1) * 8;
    const int gm = m0 + lrow;
    const bool mok = (gm < M);
    const float* Ap = g_A + (size_t)(mok ? gm : 0)*2048 + h*256 + lcol;
    const int br = t >> 3, bc = (t & 7) * 2;
    const float* Bp = Wv + (size_t)(h*32 + br)*256 + bc;
    float acc[4][4];
#pragma unroll
    for (int i = 0; i < 4; i++)
#pragma unroll
        for (int j = 0; j < 4; j++) acc[i][j] = 0.f;
    for (int k0 = 0; k0 < 256; k0 += 16) {
        float4 a0 = make_float4(0,0,0,0), a1 = a0;
        if (mok) { a0 = *(const float4*)(Ap + k0); a1 = *(const float4*)(Ap + k0 + 4); }
        float2 bv = *(const float2*)(Bp + k0);
        As[lcol+0][lrow]=a0.x; As[lcol+1][lrow]=a0.y; As[lcol+2][lrow]=a0.z; As[lcol+3][lrow]=a0.w;
        As[lcol+4][lrow]=a1.x; As[lcol+5][lrow]=a1.y; As[lcol+6][lrow]=a1.z; As[lcol+7][lrow]=a1.w;
        Bs[bc][br] = bv.x; Bs[bc+1][br] = bv.y;
        __syncthreads();
#pragma unroll
        for (int kk = 0; kk < 16; kk++) {
            float a[4], b[4];
            *(float4*)(a) = *(const float4*)&As[kk][ty*4];
            *(float4*)(b) = *(const float4*)&Bs[kk][tx*4];
#pragma unroll
            for (int i = 0; i < 4; i++)
#pragma unroll
                for (int j = 0; j < 4; j++) acc[i][j] += a[i] * b[j];
        }
        __syncthreads();
    }
#pragma unroll
    for (int i = 0; i < 4; i++) {
        int m = m0 + ty * 4 + i;
        if (m < M)
            *(float4*)&g_V[(size_t)m*256 + h*32 + tx*4] =
                make_float4(acc[i][0], acc[i][1], acc[i][2], acc[i][3]);
    }
}

extern "C" void kernel_launch(void* const* d_in, const int* in_sizes, int n_in,
                              void* d_out, int out_size) {
    const float* X    = (const float*)d_in[0];
    const int*   pidx = (const int*)d_in[1];
    const float* ccw  = (const float*)d_in[2];
    const void*  ccwm = d_in[3];
    const float* cw   = (const float*)d_in[4];
    const void*  cwm  = d_in[5];
    const float* Wself = (const float*)d_in[6];
    const float* Wpar  = (const float*)d_in[7];
    const float* Wq    = (const float*)d_in[8];
    const float* Wk    = (const float*)d_in[9];
    const float* Wv    = (const float*)d_in[10];
    const float* Wfin  = (const float*)d_in[11];
    float* out = (float*)d_out;
    const int N = in_sizes[0] / 256;

    float *pS, *pP, *pK, *pV;
    cudaGetSymbolAddress((void**)&pS, g_S);
    cudaGetSymbolAddress((void**)&pP, g_P);
    cudaGetSymbolAddress((void**)&pK, g_K);
    cudaGetSymbolAddress((void**)&pV, g_V);

    detect_kernel<<<1, 256>>>((const unsigned char*)ccwm, in_sizes[3]);

    dim3 gg((N + 127) / 128, 2);
    sgemm_nt<<<gg, 256>>>(X,   256,  nullptr, Wself, pS, N);
    sgemm_nt<<<gg, 256>>>(X,   256,  pidx,    Wpar,  pP, N);
    sgemm_nt<<<gg, 256>>>(ccw, 2048, nullptr, Wk,    pK, N);
    u_kernel<<<dim3((N + 63) / 64, 8), 256>>>(Wq, N);
    attn_kernel<<<(N + 3) / 4, 256>>>(ccw, cw, ccwm, cwm, N);
    vproj_kernel<<<dim3((N + 127) / 128, 8), 256>>>(Wv, N);
    sgemm_nt<<<gg, 256>>>(pV, 256, nullptr, Wfin, out, N);
}

// round 3
// speedup vs baseline: 1.1880x; 1.1880x over previous
#include <cuda_runtime.h>
#include <cuda_bf16.h>
#include <cstdint>
#include <cstddef>

#define MAXN 30000

__device__ float g_S[(size_t)MAXN * 256];
__device__ float g_P[(size_t)MAXN * 256];
__device__ float g_K[(size_t)MAXN * 256];
__device__ float g_V[(size_t)MAXN * 256];
__device__ float g_U[(size_t)MAXN * 8 * 256];
__device__ float g_A[(size_t)MAXN * 8 * 256];
__device__ __nv_bfloat16 g_Xh[(size_t)MAXN * 256], g_Xl[(size_t)MAXN * 256];
__device__ __nv_bfloat16 g_Mh[(size_t)MAXN * 256], g_Ml[(size_t)MAXN * 256];
__device__ __nv_bfloat16 g_Vh[(size_t)MAXN * 256], g_Vl[(size_t)MAXN * 256];
__device__ __nv_bfloat16 g_Wh[4][256 * 256], g_Wl[4][256 * 256];
__device__ int g_maskMode;

// ---------------- mask dtype detection (deterministic) ----------------
__global__ void detect_kernel(const unsigned char* __restrict__ m, int nelem) {
    __shared__ int s_nzoff, s_badf, s_anyf;
    if (threadIdx.x == 0) { s_nzoff = 0; s_badf = 0; s_anyf = 0; }
    __syncthreads();
    int words = min(nelem / 4, 1024);
    const unsigned int* wm = (const unsigned int*)m;
    int nz = 0, bf = 0, af = 0;
    for (int i = threadIdx.x; i < words; i += blockDim.x) {
        unsigned int w = wm[i];
        if (w >> 8) nz = 1;
        if (w != 0u && w != 0x3F800000u) bf = 1;
        if (w == 0x3F800000u) af = 1;
    }
    if (nz) atomicOr(&s_nzoff, 1);
    if (bf) atomicOr(&s_badf, 1);
    if (af) atomicOr(&s_anyf, 1);
    __syncthreads();
    if (threadIdx.x == 0)
        g_maskMode = (!s_badf && s_anyf) ? 2 : (!s_nzoff ? 1 : 0);
}

__device__ __forceinline__ bool mask_at(const void* p, int i, int mode) {
    if (mode == 0) return ((const unsigned char*)p)[i] != 0;
    if (mode == 1) return ((const int*)p)[i] != 0;
    return ((const float*)p)[i] != 0.0f;
}

// ---------------- fp32 -> split bf16 (hi + lo) ----------------
__global__ void split_kernel(const float* __restrict__ src, long stride,
                             __nv_bfloat16* __restrict__ hi,
                             __nv_bfloat16* __restrict__ lo, int rows) {
    int r = blockIdx.x * 4 + (threadIdx.x >> 8);
    int c = threadIdx.x & 255;
    if (r >= rows) return;
    float x = src[(size_t)r * stride + c];
    __nv_bfloat16 h = __float2bfloat16(x);
    hi[(size_t)r * 256 + c] = h;
    lo[(size_t)r * 256 + c] = __float2bfloat16(x - __bfloat162float(h));
}

// ---------------- split-bf16 tensor-core GEMM: C = A @ W^T ----------------
// C[m,n] = sum_k A[m,k]*W[n,k].  A: rows of 256 (optionally gathered).
// BM=128, BN=64, BK=32, 256 threads (8 warps, 4x2), warp tile 32x32.
#define MMA_OP(d, a, b) asm volatile( \
    "mma.sync.aligned.m16n8k16.row.col.f32.bf16.bf16.f32 " \
    "{%0,%1,%2,%3}, {%4,%5,%6,%7}, {%8,%9}, {%0,%1,%2,%3};\n" \
    : "+f"(d[0]), "+f"(d[1]), "+f"(d[2]), "+f"(d[3]) \
    : "r"(a[0]), "r"(a[1]), "r"(a[2]), "r"(a[3]), "r"(b[0]), "r"(b[1]))

__global__ __launch_bounds__(256) void gemm_bf16s(
    const __nv_bfloat16* __restrict__ Ah, const __nv_bfloat16* __restrict__ Al,
    const int* __restrict__ gather,
    const __nv_bfloat16* __restrict__ Bh, const __nv_bfloat16* __restrict__ Bl,
    float* __restrict__ C, int M) {
    __shared__ __nv_bfloat16 sAh[128][40], sAl[128][40];
    __shared__ __nv_bfloat16 sBh[64][40], sBl[64][40];
    const int t = threadIdx.x, lane = t & 31, w = t >> 5;
    const int m0 = blockIdx.x * 128, n0 = blockIdx.y * 64;
    const int wr = (w & 3) * 32, wc = (w >> 2) * 32;
    float acc[2][4][4];
#pragma unroll
    for (int i = 0; i < 2; i++)
#pragma unroll
        for (int j = 0; j < 4; j++)
#pragma unroll
            for (int q = 0; q < 4; q++) acc[i][j][q] = 0.f;

    const int ar = t >> 1, ao = (t & 1) * 16;     // A staging: row, elem offset
    const int br = t >> 2, bo = (t & 3) * 8;      // B staging: row, elem offset
    const int am = m0 + ar;
    const bool aok = (am < M);
    const long asrc = aok ? (long)(gather ? gather[am] : am) : 0;
    const __nv_bfloat16* pAh = Ah + asrc * 256 + ao;
    const __nv_bfloat16* pAl = Al + asrc * 256 + ao;
    const __nv_bfloat16* pBh = Bh + (size_t)(n0 + br) * 256 + bo;
    const __nv_bfloat16* pBl = Bl + (size_t)(n0 + br) * 256 + bo;

    for (int k0 = 0; k0 < 256; k0 += 32) {
        uint4 z = make_uint4(0, 0, 0, 0);
        uint4 vh0 = aok ? *(const uint4*)(pAh + k0)     : z;
        uint4 vh1 = aok ? *(const uint4*)(pAh + k0 + 8) : z;
        uint4 vl0 = aok ? *(const uint4*)(pAl + k0)     : z;
        uint4 vl1 = aok ? *(const uint4*)(pAl + k0 + 8) : z;
        *(uint4*)&sAh[ar][ao]     = vh0;
        *(uint4*)&sAh[ar][ao + 8] = vh1;
        *(uint4*)&sAl[ar][ao]     = vl0;
        *(uint4*)&sAl[ar][ao + 8] = vl1;
        *(uint4*)&sBh[br][bo] = *(const uint4*)(pBh + k0);
        *(uint4*)&sBl[br][bo] = *(const uint4*)(pBl + k0);
        __syncthreads();
#pragma unroll
        for (int kk = 0; kk < 32; kk += 16) {
            uint32_t afh[2][4], afl[2][4], bfh[4][2], bfl[4][2];
            const int arow = wr + (lane >> 2);
            const int acol = kk + (lane & 3) * 2;
#pragma unroll
            for (int mt = 0; mt < 2; mt++) {
                const int r0 = arow + mt * 16;
                afh[mt][0] = *(const uint32_t*)&sAh[r0][acol];
                afh[mt][1] = *(const uint32_t*)&sAh[r0 + 8][acol];
                afh[mt][2] = *(const uint32_t*)&sAh[r0][acol + 8];
                afh[mt][3] = *(const uint32_t*)&sAh[r0 + 8][acol + 8];
                afl[mt][0] = *(const uint32_t*)&sAl[r0][acol];
                afl[mt][1] = *(const uint32_t*)&sAl[r0 + 8][acol];
                afl[mt][2] = *(const uint32_t*)&sAl[r0][acol + 8];
                afl[mt][3] = *(const uint32_t*)&sAl[r0 + 8][acol + 8];
            }
#pragma unroll
            for (int nt = 0; nt < 4; nt++) {
                const int nr = wc + nt * 8 + (lane >> 2);
                bfh[nt][0] = *(const uint32_t*)&sBh[nr][acol];
                bfh[nt][1] = *(const uint32_t*)&sBh[nr][acol + 8];
                bfl[nt][0] = *(const uint32_t*)&sBl[nr][acol];
                bfl[nt][1] = *(const uint32_t*)&sBl[nr][acol + 8];
            }
#pragma unroll
            for (int mt = 0; mt < 2; mt++)
#pragma unroll
                for (int nt = 0; nt < 4; nt++) {
                    MMA_OP(acc[mt][nt], afh[mt], bfh[nt]);
                    MMA_OP(acc[mt][nt], afh[mt], bfl[nt]);
                    MMA_OP(acc[mt][nt], afl[mt], bfh[nt]);
                }
        }
        __syncthreads();
    }

    const int grp = lane >> 2, qc = (lane & 3) * 2;
#pragma unroll
    for (int mt = 0; mt < 2; mt++)
#pragma unroll
        for (int nt = 0; nt < 4; nt++) {
            const int rg = m0 + wr + mt * 16 + grp;
            const int cg = n0 + wc + nt * 8 + qc;
            if (rg < M) {
                float2 v0 = make_float2(acc[mt][nt][0], acc[mt][nt][1]);
                *(float2*)&C[(size_t)rg * 256 + cg] = v0;
            }
            if (rg + 8 < M) {
                float2 v1 = make_float2(acc[mt][nt][2], acc[mt][nt][3]);
                *(float2*)&C[(size_t)(rg + 8) * 256 + cg] = v1;
            }
        }
}

// ---------------- u[n,h,d] = sum_j K[n,h*32+j] * Wq[h*32+j,d] ----------------
__global__ void u_kernel(const float* __restrict__ Wq, int N) {
    __shared__ float Wqs[32][256];
    __shared__ float kvs[64][33];
    const int h = blockIdx.y, n0 = blockIdx.x * 64, t = threadIdx.x;
#pragma unroll
    for (int i = 0; i < 32; i++) Wqs[i][t] = Wq[(size_t)(h * 32 + i) * 256 + t];
#pragma unroll
    for (int i = 0; i < 8; i++) {
        int node = i * 8 + (t >> 5), j = t & 31, n = n0 + node;
        kvs[node][j] = (n < N) ? g_K[(size_t)n * 256 + h * 32 + j] : 0.f;
    }
    __syncthreads();
    const int txd = (t & 63) * 4, ng = (t >> 6) * 4;
    for (int p = 0; p < 4; p++) {
        const int nb = p * 16 + ng;
        float acc[4][4];
#pragma unroll
        for (int c = 0; c < 4; c++)
#pragma unroll
            for (int e = 0; e < 4; e++) acc[c][e] = 0.f;
#pragma unroll
        for (int j = 0; j < 32; j++) {
            float4 wq = *(const float4*)&Wqs[j][txd];
#pragma unroll
            for (int c = 0; c < 4; c++) {
                float kv = kvs[nb + c][j];
                acc[c][0] += kv * wq.x; acc[c][1] += kv * wq.y;
                acc[c][2] += kv * wq.z; acc[c][3] += kv * wq.w;
            }
        }
#pragma unroll
        for (int c = 0; c < 4; c++) {
            int n = n0 + nb + c;
            if (n < N)
                *(float4*)&g_U[((size_t)n * 8 + h) * 256 + txd] =
                    make_float4(acc[c][0], acc[c][1], acc[c][2], acc[c][3]);
        }
    }
}

// ---------------- attention: scores + masked softmax + aggregate ----------------
__global__ void attn_kernel(const float* __restrict__ ccw, const float* __restrict__ cw,
                            const void* __restrict__ ccwm, const void* __restrict__ cwm,
                            int N) {
    __shared__ float msg_s[18][257];
    __shared__ float u_s[8][257];
    __shared__ float sc_s[8][32];
    __shared__ float p_s[8][18];
    const int t = threadIdx.x, lane = t & 31, w = t >> 5;
    const int mode = g_maskMode;
    const float NEG = __int_as_float(0xff800000);
    for (int nl = 0; nl < 4; nl++) {
        const int n = blockIdx.x * 4 + nl;
        if (n >= N) return;
        const size_t nb = n;
#pragma unroll
        for (int i = 0; i < 8; i++) u_s[i][t] = g_U[nb * 2048 + i * 256 + t];
#pragma unroll
        for (int s = 0; s < 18; s++) {
            float v;
            if (s < 8)       v = ccw[nb * 2048 + s * 256 + t];
            else if (s == 8) v = g_S[nb * 256 + t];
            else if (s == 9) v = g_P[nb * 256 + t];
            else             v = cw[nb * 2048 + (size_t)(s - 10) * 256 + t];
            msg_s[s][t] = v;
        }
        __syncthreads();
        for (int s = 0; s < 18; s++) {
            float part = 0.f;
#pragma unroll
            for (int i = 0; i < 256; i += 32)
                part += msg_s[s][lane + i] * u_s[w][lane + i];
#pragma unroll
            for (int off = 16; off; off >>= 1)
                part += __shfl_xor_sync(0xFFFFFFFFu, part, off);
            if (lane == 0) sc_s[w][s] = part;
        }
        __syncwarp();
        {
            bool valid = false; float v = NEG;
            if (lane < 18) {
                if (lane < 8)       valid = mask_at(ccwm, n * 8 + lane, mode);
                else if (lane < 10) valid = true;
                else                valid = mask_at(cwm, n * 8 + lane - 10, mode);
                if (valid) v = sc_s[w][lane] * 0.17677669529663688f;
            }
            float mx = v;
#pragma unroll
            for (int off = 16; off; off >>= 1)
                mx = fmaxf(mx, __shfl_xor_sync(0xFFFFFFFFu, mx, off));
            float e = valid ? expf(v - mx) : 0.f;
            float sm = e;
#pragma unroll
            for (int off = 16; off; off >>= 1)
                sm += __shfl_xor_sync(0xFFFFFFFFu, sm, off);
            if (lane < 18) p_s[w][lane] = e / sm;
        }
        __syncthreads();
        float acc[8];
#pragma unroll
        for (int h = 0; h < 8; h++) acc[h] = 0.f;
#pragma unroll
        for (int s = 0; s < 18; s++) {
            float m = msg_s[s][t];
#pragma unroll
            for (int h = 0; h < 8; h++) acc[h] += p_s[h][s] * m;
        }
#pragma unroll
        for (int h = 0; h < 8; h++) g_A[(nb * 8 + h) * 256 + t] = acc[h];
        __syncthreads();
    }
}

// ---------------- V[n,h*32+d'] = sum_d Wv[h*32+d',d] * agg[n,h,d] ----------------
__global__ void vproj_kernel(const float* __restrict__ Wv, int M) {
    __shared__ float As[16][132];
    __shared__ float Bs[16][36];
    const int h = blockIdx.y, m0 = blockIdx.x * 128, t = threadIdx.x;
    const int tx = t & 7, ty = t >> 3;
    const int lrow = t >> 1, lcol = (t & 1) * 8;
    const int gm = m0 + lrow;
    const bool mok = (gm < M);
    const float* Ap = g_A + (size_t)(mok ? gm : 0) * 2048 + h * 256 + lcol;
    const int br = t >> 3, bc = (t & 7) * 2;
    const float* Bp = Wv + (size_t)(h * 32 + br) * 256 + bc;
    float acc[4][4];
#pragma unroll
    for (int i = 0; i < 4; i++)
#pragma unroll
        for (int j = 0; j < 4; j++) acc[i][j] = 0.f;
    for (int k0 = 0; k0 < 256; k0 += 16) {
        float4 a0 = make_float4(0, 0, 0, 0), a1 = a0;
        if (mok) { a0 = *(const float4*)(Ap + k0); a1 = *(const float4*)(Ap + k0 + 4); }
        float2 bv = *(const float2*)(Bp + k0);
        As[lcol + 0][lrow] = a0.x; As[lcol + 1][lrow] = a0.y;
        As[lcol + 2][lrow] = a0.z; As[lcol + 3][lrow] = a0.w;
        As[lcol + 4][lrow] = a1.x; As[lcol + 5][lrow] = a1.y;
        As[lcol + 6][lrow] = a1.z; As[lcol + 7][lrow] = a1.w;
        Bs[bc][br] = bv.x; Bs[bc + 1][br] = bv.y;
        __syncthreads();
#pragma unroll
        for (int kk = 0; kk < 16; kk++) {
            float a[4], b[4];
            *(float4*)(a) = *(const float4*)&As[kk][ty * 4];
            *(float4*)(b) = *(const float4*)&Bs[kk][tx * 4];
#pragma unroll
            for (int i = 0; i < 4; i++)
#pragma unroll
                for (int j = 0; j < 4; j++) acc[i][j] += a[i] * b[j];
        }
        __syncthreads();
    }
#pragma unroll
    for (int i = 0; i < 4; i++) {
        int m = m0 + ty * 4 + i;
        if (m < M)
            *(float4*)&g_V[(size_t)m * 256 + h * 32 + tx * 4] =
                make_float4(acc[i][0], acc[i][1], acc[i][2], acc[i][3]);
    }
}

extern "C" void kernel_launch(void* const* d_in, const int* in_sizes, int n_in,
                              void* d_out, int out_size) {
    const float* X    = (const float*)d_in[0];
    const int*   pidx = (const int*)d_in[1];
    const float* ccw  = (const float*)d_in[2];
    const void*  ccwm = d_in[3];
    const float* cw   = (const float*)d_in[4];
    const void*  cwm  = d_in[5];
    const float* Wself = (const float*)d_in[6];
    const float* Wpar  = (const float*)d_in[7];
    const float* Wq    = (const float*)d_in[8];
    const float* Wk    = (const float*)d_in[9];
    const float* Wv    = (const float*)d_in[10];
    const float* Wfin  = (const float*)d_in[11];
    float* out = (float*)d_out;
    const int N = in_sizes[0] / 256;

    float *pS, *pP, *pK, *pV;
    __nv_bfloat16 *pXh, *pXl, *pMh, *pMl, *pVh, *pVl, *pWh, *pWl;
    cudaGetSymbolAddress((void**)&pS, g_S);
    cudaGetSymbolAddress((void**)&pP, g_P);
    cudaGetSymbolAddress((void**)&pK, g_K);
    cudaGetSymbolAddress((void**)&pV, g_V);
    cudaGetSymbolAddress((void**)&pXh, g_Xh);
    cudaGetSymbolAddress((void**)&pXl, g_Xl);
    cudaGetSymbolAddress((void**)&pMh, g_Mh);
    cudaGetSymbolAddress((void**)&pMl, g_Ml);
    cudaGetSymbolAddress((void**)&pVh, g_Vh);
    cudaGetSymbolAddress((void**)&pVl, g_Vl);
    cudaGetSymbolAddress((void**)&pWh, g_Wh);
    cudaGetSymbolAddress((void**)&pWl, g_Wl);

    detect_kernel<<<1, 256>>>((const unsigned char*)ccwm, in_sizes[3]);

    const int WSZ = 256 * 256;
    int rb = (N + 3) / 4;
    split_kernel<<<rb, 1024>>>(X,   256,  pXh, pXl, N);
    split_kernel<<<rb, 1024>>>(ccw, 2048, pMh, pMl, N);
    split_kernel<<<64, 1024>>>(Wself, 256, pWh + 0 * WSZ, pWl + 0 * WSZ, 256);
    split_kernel<<<64, 1024>>>(Wpar,  256, pWh + 1 * WSZ, pWl + 1 * WSZ, 256);
    split_kernel<<<64, 1024>>>(Wk,    256, pWh + 2 * WSZ, pWl + 2 * WSZ, 256);
    split_kernel<<<64, 1024>>>(Wfin,  256, pWh + 3 * WSZ, pWl + 3 * WSZ, 256);

    dim3 gg((N + 127) / 128, 4);
    gemm_bf16s<<<gg, 256>>>(pXh, pXl, nullptr, pWh + 0 * WSZ, pWl + 0 * WSZ, pS, N);
    gemm_bf16s<<<gg, 256>>>(pXh, pXl, pidx,    pWh + 1 * WSZ, pWl + 1 * WSZ, pP, N);
    gemm_bf16s<<<gg, 256>>>(pMh, pMl, nullptr, pWh + 2 * WSZ, pWl + 2 * WSZ, pK, N);

    u_kernel<<<dim3((N + 63) / 64, 8), 256>>>(Wq, N);
    attn_kernel<<<(N + 3) / 4, 256>>>(ccw, cw, ccwm, cwm, N);
    vproj_kernel<<<dim3((N + 127) / 128, 8), 256>>>(Wv, N);

    split_kernel<<<rb, 1024>>>(pV, 256, pVh, pVl, N);
    gemm_bf16s<<<gg, 256>>>(pVh, pVl, nullptr, pWh + 3 * WSZ, pWl + 3 * WSZ, out, N);
}

// round 5
// speedup vs baseline: 1.2108x; 1.0191x over previous
#include <cuda_runtime.h>
#include <cuda_bf16.h>
#include <cstdint>
#include <cstddef>

#define MAXN 30000

__device__ float g_S[(size_t)MAXN * 256];
__device__ float g_P[(size_t)MAXN * 256];
__device__ float g_K[(size_t)MAXN * 256];
__device__ float g_V[(size_t)MAXN * 256];
__device__ float g_U[(size_t)MAXN * 8 * 256];
__device__ float g_A[(size_t)MAXN * 8 * 256];
__device__ __nv_bfloat16 g_Wh[4][256 * 256], g_Wl[4][256 * 256];
__device__ __nv_bfloat16 g_WqTh[256 * 256], g_WqTl[256 * 256];
__device__ int g_maskMode;

// ---------------- mask dtype detection (deterministic) ----------------
__global__ void detect_kernel(const unsigned char* __restrict__ m, int nelem) {
    __shared__ int s_nzoff, s_badf, s_anyf;
    if (threadIdx.x == 0) { s_nzoff = 0; s_badf = 0; s_anyf = 0; }
    __syncthreads();
    int words = min(nelem / 4, 1024);
    const unsigned int* wm = (const unsigned int*)m;
    int nz = 0, bf = 0, af = 0;
    for (int i = threadIdx.x; i < words; i += blockDim.x) {
        unsigned int w = wm[i];
        if (w >> 8) nz = 1;
        if (w != 0u && w != 0x3F800000u) bf = 1;
        if (w == 0x3F800000u) af = 1;
    }
    if (nz) atomicOr(&s_nzoff, 1);
    if (bf) atomicOr(&s_badf, 1);
    if (af) atomicOr(&s_anyf, 1);
    __syncthreads();
    if (threadIdx.x == 0)
        g_maskMode = (!s_badf && s_anyf) ? 2 : (!s_nzoff ? 1 : 0);
}

__device__ __forceinline__ bool mask_at(const void* p, int i, int mode) {
    if (mode == 0) return ((const unsigned char*)p)[i] != 0;
    if (mode == 1) return ((const int*)p)[i] != 0;
    return ((const float*)p)[i] != 0.0f;
}

// ---------------- fp32 -> split bf16 helpers ----------------
__device__ __forceinline__ void split8(float4 a, float4 b, uint4& h, uint4& l) {
    float x[8] = {a.x, a.y, a.z, a.w, b.x, b.y, b.z, b.w};
    uint32_t hw[4], lw[4];
#pragma unroll
    for (int p = 0; p < 4; p++) {
        __nv_bfloat16 h0 = __float2bfloat16(x[2 * p]);
        __nv_bfloat16 h1 = __float2bfloat16(x[2 * p + 1]);
        __nv_bfloat16 l0 = __float2bfloat16(x[2 * p] - __bfloat162float(h0));
        __nv_bfloat16 l1 = __float2bfloat16(x[2 * p + 1] - __bfloat162float(h1));
        hw[p] = ((uint32_t)__bfloat16_as_ushort(h1) << 16) | __bfloat16_as_ushort(h0);
        lw[p] = ((uint32_t)__bfloat16_as_ushort(l1) << 16) | __bfloat16_as_ushort(l0);
    }
    h = make_uint4(hw[0], hw[1], hw[2], hw[3]);
    l = make_uint4(lw[0], lw[1], lw[2], lw[3]);
}

__device__ __forceinline__ void split4(float4 a, uint2& h, uint2& l) {
    float x[4] = {a.x, a.y, a.z, a.w};
    uint32_t hw[2], lw[2];
#pragma unroll
    for (int p = 0; p < 2; p++) {
        __nv_bfloat16 h0 = __float2bfloat16(x[2 * p]);
        __nv_bfloat16 h1 = __float2bfloat16(x[2 * p + 1]);
        __nv_bfloat16 l0 = __float2bfloat16(x[2 * p] - __bfloat162float(h0));
        __nv_bfloat16 l1 = __float2bfloat16(x[2 * p + 1] - __bfloat162float(h1));
        hw[p] = ((uint32_t)__bfloat16_as_ushort(h1) << 16) | __bfloat16_as_ushort(h0);
        lw[p] = ((uint32_t)__bfloat16_as_ushort(l1) << 16) | __bfloat16_as_ushort(l0);
    }
    h = make_uint2(hw[0], hw[1]);
    l = make_uint2(lw[0], lw[1]);
}

// split weights (row-major, stride 256)
__global__ void split_kernel(const float* __restrict__ src,
                             __nv_bfloat16* __restrict__ hi,
                             __nv_bfloat16* __restrict__ lo, int rows) {
    int r = blockIdx.x * 4 + (threadIdx.x >> 8);
    int c = threadIdx.x & 255;
    if (r >= rows) return;
    float x = src[(size_t)r * 256 + c];
    __nv_bfloat16 h = __float2bfloat16(x);
    hi[(size_t)r * 256 + c] = h;
    lo[(size_t)r * 256 + c] = __float2bfloat16(x - __bfloat162float(h));
}

// WqT[i][o] = Wq[o][i], split
__global__ void wq_prep(const float* __restrict__ Wq) {
    int i = blockIdx.x * 4 + (threadIdx.x >> 8);
    int o = threadIdx.x & 255;
    float x = Wq[(size_t)o * 256 + i];
    __nv_bfloat16 h = __float2bfloat16(x);
    g_WqTh[(size_t)i * 256 + o] = h;
    g_WqTl[(size_t)i * 256 + o] = __float2bfloat16(x - __bfloat162float(h));
}

#define MMA_OP(d, a, b) asm volatile( \
    "mma.sync.aligned.m16n8k16.row.col.f32.bf16.bf16.f32 " \
    "{%0,%1,%2,%3}, {%4,%5,%6,%7}, {%8,%9}, {%0,%1,%2,%3};\n" \
    : "+f"(d[0]), "+f"(d[1]), "+f"(d[2]), "+f"(d[3]) \
    : "r"(a[0]), "r"(a[1]), "r"(a[2]), "r"(a[3]), "r"(b[0]), "r"(b[1]))

// ---------------- dense GEMM: C = A(fp32, split in-kernel) @ W^T(pre-split) ----
// BM=128, BN=64, BK=32, 256 thr, warp tile 32x32.
__global__ __launch_bounds__(256) void gemm_f32s(
    const float* __restrict__ A, long lda, const int* __restrict__ gather,
    const __nv_bfloat16* __restrict__ Bh, const __nv_bfloat16* __restrict__ Bl,
    float* __restrict__ C, int M) {
    __shared__ __nv_bfloat16 sAh[128][40], sAl[128][40];
    __shared__ __nv_bfloat16 sBh[64][40], sBl[64][40];
    const int t = threadIdx.x, lane = t & 31, w = t >> 5;
    const int m0 = blockIdx.x * 128, n0 = blockIdx.y * 64;
    const int wr = (w & 3) * 32, wc = (w >> 2) * 32;
    float acc[2][4][4];
#pragma unroll
    for (int i = 0; i < 2; i++)
#pragma unroll
        for (int j = 0; j < 4; j++)
#pragma unroll
            for (int q = 0; q < 4; q++) acc[i][j][q] = 0.f;

    const int ar = t >> 1, ao = (t & 1) * 16;
    const int br = t >> 2, bo = (t & 3) * 8;
    const int am = m0 + ar;
    const bool aok = (am < M);
    const long asrc = aok ? (long)(gather ? gather[am] : am) : 0;
    const float* pA = A + asrc * lda + ao;
    const __nv_bfloat16* pBh = Bh + (size_t)(n0 + br) * 256 + bo;
    const __nv_bfloat16* pBl = Bl + (size_t)(n0 + br) * 256 + bo;

    for (int k0 = 0; k0 < 256; k0 += 32) {
        float4 z = make_float4(0, 0, 0, 0);
        float4 a0 = aok ? *(const float4*)(pA + k0)      : z;
        float4 a1 = aok ? *(const float4*)(pA + k0 + 4)  : z;
        float4 a2 = aok ? *(const float4*)(pA + k0 + 8)  : z;
        float4 a3 = aok ? *(const float4*)(pA + k0 + 12) : z;
        uint4 h0, l0, h1, l1;
        split8(a0, a1, h0, l0);
        split8(a2, a3, h1, l1);
        *(uint4*)&sAh[ar][ao]     = h0;
        *(uint4*)&sAh[ar][ao + 8] = h1;
        *(uint4*)&sAl[ar][ao]     = l0;
        *(uint4*)&sAl[ar][ao + 8] = l1;
        *(uint4*)&sBh[br][bo] = *(const uint4*)(pBh + k0);
        *(uint4*)&sBl[br][bo] = *(const uint4*)(pBl + k0);
        __syncthreads();
#pragma unroll
        for (int kk = 0; kk < 32; kk += 16) {
            uint32_t afh[2][4], afl[2][4], bfh[4][2], bfl[4][2];
            const int arow = wr + (lane >> 2);
            const int acol = kk + (lane & 3) * 2;
#pragma unroll
            for (int mt = 0; mt < 2; mt++) {
                const int r0 = arow + mt * 16;
                afh[mt][0] = *(const uint32_t*)&sAh[r0][acol];
                afh[mt][1] = *(const uint32_t*)&sAh[r0 + 8][acol];
                afh[mt][2] = *(const uint32_t*)&sAh[r0][acol + 8];
                afh[mt][3] = *(const uint32_t*)&sAh[r0 + 8][acol + 8];
                afl[mt][0] = *(const uint32_t*)&sAl[r0][acol];
                afl[mt][1] = *(const uint32_t*)&sAl[r0 + 8][acol];
                afl[mt][2] = *(const uint32_t*)&sAl[r0][acol + 8];
                afl[mt][3] = *(const uint32_t*)&sAl[r0 + 8][acol + 8];
            }
#pragma unroll
            for (int nt = 0; nt < 4; nt++) {
                const int nr = wc + nt * 8 + (lane >> 2);
                bfh[nt][0] = *(const uint32_t*)&sBh[nr][acol];
                bfh[nt][1] = *(const uint32_t*)&sBh[nr][acol + 8];
                bfl[nt][0] = *(const uint32_t*)&sBl[nr][acol];
                bfl[nt][1] = *(const uint32_t*)&sBl[nr][acol + 8];
            }
#pragma unroll
            for (int mt = 0; mt < 2; mt++)
#pragma unroll
                for (int nt = 0; nt < 4; nt++) {
                    MMA_OP(acc[mt][nt], afh[mt], bfh[nt]);
                    MMA_OP(acc[mt][nt], afh[mt], bfl[nt]);
                    MMA_OP(acc[mt][nt], afl[mt], bfh[nt]);
                }
        }
        __syncthreads();
    }
    const int grp = lane >> 2, qc = (lane & 3) * 2;
#pragma unroll
    for (int mt = 0; mt < 2; mt++)
#pragma unroll
        for (int nt = 0; nt < 4; nt++) {
            const int rg = m0 + wr + mt * 16 + grp;
            const int cg = n0 + wc + nt * 8 + qc;
            if (rg < M)
                *(float2*)&C[(size_t)rg * 256 + cg] =
                    make_float2(acc[mt][nt][0], acc[mt][nt][1]);
            if (rg + 8 < M)
                *(float2*)&C[(size_t)(rg + 8) * 256 + cg] =
                    make_float2(acc[mt][nt][2], acc[mt][nt][3]);
        }
}

// ---------------- u via tensor cores: U[n, h*256+i] = sum_j K[n,h*32+j]*WqT[i][h*32+j]
// BM=128 nodes, BN=64 i-cols, K=32. grid (nodes/128, 4, 8heads)
__global__ __launch_bounds__(256) void u_tc(int M) {
    __shared__ __nv_bfloat16 sAh[128][40], sAl[128][40];
    __shared__ __nv_bfloat16 sBh[64][40], sBl[64][40];
    const int t = threadIdx.x, lane = t & 31, w = t >> 5;
    const int m0 = blockIdx.x * 128, i0 = blockIdx.y * 64, h = blockIdx.z;
    const int wr = (w & 3) * 32, wc = (w >> 2) * 32;
    float acc[2][4][4];
#pragma unroll
    for (int i = 0; i < 2; i++)
#pragma unroll
        for (int j = 0; j < 4; j++)
#pragma unroll
            for (int q = 0; q < 4; q++) acc[i][j][q] = 0.f;

    const int ar = t >> 1, ao = (t & 1) * 16;
    const int br = t >> 2, bo = (t & 3) * 8;
    const int am = m0 + ar;
    const bool aok = (am < M);
    {
        float4 z = make_float4(0, 0, 0, 0);
        const float* pA = g_K + (size_t)(aok ? am : 0) * 256 + h * 32 + ao;
        float4 a0 = aok ? *(const float4*)(pA)      : z;
        float4 a1 = aok ? *(const float4*)(pA + 4)  : z;
        float4 a2 = aok ? *(const float4*)(pA + 8)  : z;
        float4 a3 = aok ? *(const float4*)(pA + 12) : z;
        uint4 h0, l0, h1, l1;
        split8(a0, a1, h0, l0);
        split8(a2, a3, h1, l1);
        *(uint4*)&sAh[ar][ao]     = h0;
        *(uint4*)&sAh[ar][ao + 8] = h1;
        *(uint4*)&sAl[ar][ao]     = l0;
        *(uint4*)&sAl[ar][ao + 8] = l1;
        *(uint4*)&sBh[br][bo] = *(const uint4*)&g_WqTh[(size_t)(i0 + br) * 256 + h * 32 + bo];
        *(uint4*)&sBl[br][bo] = *(const uint4*)&g_WqTl[(size_t)(i0 + br) * 256 + h * 32 + bo];
    }
    __syncthreads();
#pragma unroll
    for (int kk = 0; kk < 32; kk += 16) {
        uint32_t afh[2][4], afl[2][4], bfh[4][2], bfl[4][2];
        const int arow = wr + (lane >> 2);
        const int acol = kk + (lane & 3) * 2;
#pragma unroll
        for (int mt = 0; mt < 2; mt++) {
            const int r0 = arow + mt * 16;
            afh[mt][0] = *(const uint32_t*)&sAh[r0][acol];
            afh[mt][1] = *(const uint32_t*)&sAh[r0 + 8][acol];
            afh[mt][2] = *(const uint32_t*)&sAh[r0][acol + 8];
            afh[mt][3] = *(const uint32_t*)&sAh[r0 + 8][acol + 8];
            afl[mt][0] = *(const uint32_t*)&sAl[r0][acol];
            afl[mt][1] = *(const uint32_t*)&sAl[r0 + 8][acol];
            afl[mt][2] = *(const uint32_t*)&sAl[r0][acol + 8];
            afl[mt][3] = *(const uint32_t*)&sAl[r0 + 8][acol + 8];
        }
#pragma unroll
        for (int nt = 0; nt < 4; nt++) {
            const int nr = wc + nt * 8 + (lane >> 2);
            bfh[nt][0] = *(const uint32_t*)&sBh[nr][acol];
            bfh[nt][1] = *(const uint32_t*)&sBh[nr][acol + 8];
            bfl[nt][0] = *(const uint32_t*)&sBl[nr][acol];
            bfl[nt][1] = *(const uint32_t*)&sBl[nr][acol + 8];
        }
#pragma unroll
        for (int mt = 0; mt < 2; mt++)
#pragma unroll
            for (int nt = 0; nt < 4; nt++) {
                MMA_OP(acc[mt][nt], afh[mt], bfh[nt]);
                MMA_OP(acc[mt][nt], afh[mt], bfl[nt]);
                MMA_OP(acc[mt][nt], afl[mt], bfh[nt]);
            }
    }
    const int grp = lane >> 2, qc = (lane & 3) * 2;
#pragma unroll
    for (int mt = 0; mt < 2; mt++)
#pragma unroll
        for (int nt = 0; nt < 4; nt++) {
            const int rg = m0 + wr + mt * 16 + grp;
            const int cg = h * 256 + i0 + wc + nt * 8 + qc;
            if (rg < M)
                *(float2*)&g_U[(size_t)rg * 2048 + cg] =
                    make_float2(acc[mt][nt][0], acc[mt][nt][1]);
            if (rg + 8 < M)
                *(float2*)&g_U[(size_t)(rg + 8) * 2048 + cg] =
                    make_float2(acc[mt][nt][2], acc[mt][nt][3]);
        }
}

// ---------------- vproj via tensor cores: V[n, h*32+o] = sum_d A[n,h,d]*Wv[h*32+o,d]
// BM=128, BN=32, BK=32, 8 k-iters. grid (nodes/128, 8heads). warp tile 32x16.
__global__ __launch_bounds__(256) void vproj_tc(const float* __restrict__ Wv, int M) {
    __shared__ __nv_bfloat16 sAh[128][40], sAl[128][40];
    __shared__ __nv_bfloat16 sBh[32][40], sBl[32][40];
    const int t = threadIdx.x, lane = t & 31, w = t >> 5;
    const int m0 = blockIdx.x * 128, h = blockIdx.y;
    const int wr = (w & 3) * 32, wc = (w >> 2) * 16;
    float acc[2][2][4];
#pragma unroll
    for (int i = 0; i < 2; i++)
#pragma unroll
        for (int j = 0; j < 2; j++)
#pragma unroll
            for (int q = 0; q < 4; q++) acc[i][j][q] = 0.f;

    const int ar = t >> 1, ao = (t & 1) * 16;
    const int br = t >> 3, bo = (t & 7) * 4;
    const int am = m0 + ar;
    const bool aok = (am < M);
    const float* pA = g_A + (size_t)(aok ? am : 0) * 2048 + h * 256 + ao;
    const float* pB = Wv + (size_t)(h * 32 + br) * 256 + bo;

    for (int k0 = 0; k0 < 256; k0 += 32) {
        float4 z = make_float4(0, 0, 0, 0);
        float4 a0 = aok ? *(const float4*)(pA + k0)      : z;
        float4 a1 = aok ? *(const float4*)(pA + k0 + 4)  : z;
        float4 a2 = aok ? *(const float4*)(pA + k0 + 8)  : z;
        float4 a3 = aok ? *(const float4*)(pA + k0 + 12) : z;
        uint4 h0, l0, h1, l1;
        split8(a0, a1, h0, l0);
        split8(a2, a3, h1, l1);
        *(uint4*)&sAh[ar][ao]     = h0;
        *(uint4*)&sAh[ar][ao + 8] = h1;
        *(uint4*)&sAl[ar][ao]     = l0;
        *(uint4*)&sAl[ar][ao + 8] = l1;
        float4 bv = *(const float4*)(pB + k0);
        uint2 bh, bl;
        split4(bv, bh, bl);
        *(uint2*)&sBh[br][bo] = bh;
        *(uint2*)&sBl[br][bo] = bl;
        __syncthreads();
#pragma unroll
        for (int kk = 0; kk < 32; kk += 16) {
            uint32_t afh[2][4], afl[2][4], bfh[2][2], bfl[2][2];
            const int arow = wr + (lane >> 2);
            const int acol = kk + (lane & 3) * 2;
#pragma unroll
            for (int mt = 0; mt < 2; mt++) {
                const int r0 = arow + mt * 16;
                afh[mt][0] = *(const uint32_t*)&sAh[r0][acol];
                afh[mt][1] = *(const uint32_t*)&sAh[r0 + 8][acol];
                afh[mt][2] = *(const uint32_t*)&sAh[r0][acol + 8];
                afh[mt][3] = *(const uint32_t*)&sAh[r0 + 8][acol + 8];
                afl[mt][0] = *(const uint32_t*)&sAl[r0][acol];
                afl[mt][1] = *(const uint32_t*)&sAl[r0 + 8][acol];
                afl[mt][2] = *(const uint32_t*)&sAl[r0][acol + 8];
                afl[mt][3] = *(const uint32_t*)&sAl[r0 + 8][acol + 8];
            }
#pragma unroll
            for (int nt = 0; nt < 2; nt++) {
                const int nr = wc + nt * 8 + (lane >> 2);
                bfh[nt][0] = *(const uint32_t*)&sBh[nr][acol];
                bfh[nt][1] = *(const uint32_t*)&sBh[nr][acol + 8];
                bfl[nt][0] = *(const uint32_t*)&sBl[nr][acol];
                bfl[nt][1] = *(const uint32_t*)&sBl[nr][acol + 8];
            }
#pragma unroll
            for (int mt = 0; mt < 2; mt++)
#pragma unroll
                for (int nt = 0; nt < 2; nt++) {
                    MMA_OP(acc[mt][nt], afh[mt], bfh[nt]);
                    MMA_OP(acc[mt][nt], afh[mt], bfl[nt]);
                    MMA_OP(acc[mt][nt], afl[mt], bfh[nt]);
                }
        }
        __syncthreads();
    }
    const int grp = lane >> 2, qc = (lane & 3) * 2;
#pragma unroll
    for (int mt = 0; mt < 2; mt++)
#pragma unroll
        for (int nt = 0; nt < 2; nt++) {
            const int rg = m0 + wr + mt * 16 + grp;
            const int cg = h * 32 + wc + nt * 8 + qc;
            if (rg < M)
                *(float2*)&g_V[(size_t)rg * 256 + cg] =
                    make_float2(acc[mt][nt][0], acc[mt][nt][1]);
            if (rg + 8 < M)
                *(float2*)&g_V[(size_t)(rg + 8) * 256 + cg] =
                    make_float2(acc[mt][nt][2], acc[mt][nt][3]);
        }
}

// ---------------- attention: scores + masked softmax + aggregate ----------------
// warps 0-3 own 2 heads each, u in registers (from gmem); lane owns 8 contiguous d.
__global__ void attn_kernel(const float* __restrict__ ccw, const float* __restrict__ cw,
                            const void* __restrict__ ccwm, const void* __restrict__ cwm,
                            int N) {
    __shared__ float msg_s[18][264];
    __shared__ float sc_s[8][20];
    __shared__ float p_s[8][20];
    const int t = threadIdx.x, lane = t & 31, w = t >> 5;
    const int mode = g_maskMode;
    const float NEG = __int_as_float(0xff800000);
    for (int nl = 0; nl < 4; nl++) {
        const int n = blockIdx.x * 4 + nl;
        if (n >= N) return;
        const size_t nb = n;
        // load 18 msg rows (float4 vectorized)
#pragma unroll
        for (int p = 0; p < 5; p++) {
            int idx = p * 256 + t;
            if (idx < 18 * 64) {
                int s = idx >> 6, q = (idx & 63) * 4;
                const float* src;
                if (s < 8)       src = ccw + nb * 2048 + (size_t)s * 256;
                else if (s == 8) src = g_S + nb * 256;
                else if (s == 9) src = g_P + nb * 256;
                else             src = cw + nb * 2048 + (size_t)(s - 10) * 256;
                *(float4*)&msg_s[s][q] = *(const float4*)&src[q];
            }
        }
        __syncthreads();
        if (w < 4) {
            const int h0 = 2 * w, h1 = 2 * w + 1;
            float u0[8], u1[8];
            *(float4*)&u0[0] = *(const float4*)&g_U[nb * 2048 + (size_t)h0 * 256 + lane * 8];
            *(float4*)&u0[4] = *(const float4*)&g_U[nb * 2048 + (size_t)h0 * 256 + lane * 8 + 4];
            *(float4*)&u1[0] = *(const float4*)&g_U[nb * 2048 + (size_t)h1 * 256 + lane * 8];
            *(float4*)&u1[4] = *(const float4*)&g_U[nb * 2048 + (size_t)h1 * 256 + lane * 8 + 4];
#pragma unroll
            for (int s = 0; s < 18; s++) {
                float4 a = *(const float4*)&msg_s[s][lane * 8];
                float4 b = *(const float4*)&msg_s[s][lane * 8 + 4];
                float p0 = a.x * u0[0] + a.y * u0[1] + a.z * u0[2] + a.w * u0[3]
                         + b.x * u0[4] + b.y * u0[5] + b.z * u0[6] + b.w * u0[7];
                float p1 = a.x * u1[0] + a.y * u1[1] + a.z * u1[2] + a.w * u1[3]
                         + b.x * u1[4] + b.y * u1[5] + b.z * u1[6] + b.w * u1[7];
#pragma unroll
                for (int off = 16; off; off >>= 1) {
                    p0 += __shfl_xor_sync(0xFFFFFFFFu, p0, off);
                    p1 += __shfl_xor_sync(0xFFFFFFFFu, p1, off);
                }
                if (lane == 0) { sc_s[h0][s] = p0; sc_s[h1][s] = p1; }
            }
            __syncwarp();
            // softmax for 2 heads
            bool valid = false;
            if (lane < 18) {
                if (lane < 8)       valid = mask_at(ccwm, n * 8 + lane, mode);
                else if (lane < 10) valid = true;
                else                valid = mask_at(cwm, n * 8 + lane - 10, mode);
            }
#pragma unroll
            for (int hh = 0; hh < 2; hh++) {
                const int hcur = h0 + hh;
                float v = NEG;
                if (lane < 18 && valid) v = sc_s[hcur][lane] * 0.17677669529663688f;
                float mx = v;
#pragma unroll
                for (int off = 16; off; off >>= 1)
                    mx = fmaxf(mx, __shfl_xor_sync(0xFFFFFFFFu, mx, off));
                float e = (lane < 18 && valid) ? expf(v - mx) : 0.f;
                float sm = e;
#pragma unroll
                for (int off = 16; off; off >>= 1)
                    sm += __shfl_xor_sync(0xFFFFFFFFu, sm, off);
                if (lane < 18) p_s[hcur][lane] = e / sm;
            }
        }
        __syncthreads();
        float acc[8];
#pragma unroll
        for (int h = 0; h < 8; h++) acc[h] = 0.f;
#pragma unroll
        for (int s = 0; s < 18; s++) {
            float m = msg_s[s][t];
#pragma unroll
            for (int h = 0; h < 8; h++) acc[h] += p_s[h][s] * m;
        }
#pragma unroll
        for (int h = 0; h < 8; h++) g_A[(nb * 8 + h) * 256 + t] = acc[h];
        __syncthreads();
    }
}

extern "C" void kernel_launch(void* const* d_in, const int* in_sizes, int n_in,
                              void* d_out, int out_size) {
    const float* X    = (const float*)d_in[0];
    const int*   pidx = (const int*)d_in[1];
    const float* ccw  = (const float*)d_in[2];
    const void*  ccwm = d_in[3];
    const float* cw   = (const float*)d_in[4];
    const void*  cwm  = d_in[5];
    const float* Wself = (const float*)d_in[6];
    const float* Wpar  = (const float*)d_in[7];
    const float* Wq    = (const float*)d_in[8];
    const float* Wk    = (const float*)d_in[9];
    const float* Wv    = (const float*)d_in[10];
    const float* Wfin  = (const float*)d_in[11];
    float* out = (float*)d_out;
    const int N = in_sizes[0] / 256;

    float *pS, *pP, *pK, *pV;
    __nv_bfloat16 *pWh, *pWl;
    cudaGetSymbolAddress((void**)&pS, g_S);
    cudaGetSymbolAddress((void**)&pP, g_P);
    cudaGetSymbolAddress((void**)&pK, g_K);
    cudaGetSymbolAddress((void**)&pV, g_V);
    cudaGetSymbolAddress((void**)&pWh, g_Wh);
    cudaGetSymbolAddress((void**)&pWl, g_Wl);

    detect_kernel<<<1, 256>>>((const unsigned char*)ccwm, in_sizes[3]);

    const int WSZ = 256 * 256;
    split_kernel<<<64, 1024>>>(Wself, pWh + 0 * WSZ, pWl + 0 * WSZ, 256);
    split_kernel<<<64, 1024>>>(Wpar,  pWh + 1 * WSZ, pWl + 1 * WSZ, 256);
    split_kernel<<<64, 1024>>>(Wk,    pWh + 2 * WSZ, pWl + 2 * WSZ, 256);
    split_kernel<<<64, 1024>>>(Wfin,  pWh + 3 * WSZ, pWl + 3 * WSZ, 256);
    wq_prep<<<64, 1024>>>(Wq);

    dim3 gg((N + 127) / 128, 4);
    gemm_f32s<<<gg, 256>>>(X,   256,  nullptr, pWh + 0 * WSZ, pWl + 0 * WSZ, pS, N);
    gemm_f32s<<<gg, 256>>>(X,   256,  pidx,    pWh + 1 * WSZ, pWl + 1 * WSZ, pP, N);
    gemm_f32s<<<gg, 256>>>(ccw, 2048, nullptr, pWh + 2 * WSZ, pWl + 2 * WSZ, pK, N);

    u_tc<<<dim3((N + 127) / 128, 4, 8), 256>>>(N);
    attn_kernel<<<(N + 3) / 4, 256>>>(ccw, cw, ccwm, cwm, N);
    vproj_tc<<<dim3((N + 127) / 128, 8), 256>>>(Wv, N);

    gemm_f32s<<<gg, 256>>>(pV, 256, nullptr, pWh + 3 * WSZ, pWl + 3 * WSZ, out, N);
}

// round 6
// speedup vs baseline: 1.7372x; 1.4348x over previous
#include <cuda_runtime.h>
#include <cuda_bf16.h>
#include <cstdint>
#include <cstddef>

#define MAXN 30000

__device__ float g_S[(size_t)MAXN * 256];
__device__ float g_P[(size_t)MAXN * 256];
__device__ float g_K[(size_t)MAXN * 256];
__device__ float g_V[(size_t)MAXN * 256];
__device__ float g_U[(size_t)MAXN * 8 * 256];
__device__ float g_A[(size_t)MAXN * 8 * 256];
__device__ __nv_bfloat16 g_Wh[4][256 * 256], g_Wl[4][256 * 256];
__device__ __nv_bfloat16 g_WqTh[256 * 256], g_WqTl[256 * 256];
__device__ int g_maskMode;

// ---------------- mask dtype detection (deterministic) ----------------
__global__ void detect_kernel(const unsigned char* __restrict__ m, int nelem) {
    __shared__ int s_nzoff, s_badf, s_anyf;
    if (threadIdx.x == 0) { s_nzoff = 0; s_badf = 0; s_anyf = 0; }
    __syncthreads();
    int words = min(nelem / 4, 1024);
    const unsigned int* wm = (const unsigned int*)m;
    int nz = 0, bf = 0, af = 0;
    for (int i = threadIdx.x; i < words; i += blockDim.x) {
        unsigned int w = wm[i];
        if (w >> 8) nz = 1;
        if (w != 0u && w != 0x3F800000u) bf = 1;
        if (w == 0x3F800000u) af = 1;
    }
    if (nz) atomicOr(&s_nzoff, 1);
    if (bf) atomicOr(&s_badf, 1);
    if (af) atomicOr(&s_anyf, 1);
    __syncthreads();
    if (threadIdx.x == 0)
        g_maskMode = (!s_badf && s_anyf) ? 2 : (!s_nzoff ? 1 : 0);
}

__device__ __forceinline__ bool mask_at(const void* p, int i, int mode) {
    if (mode == 0) return ((const unsigned char*)p)[i] != 0;
    if (mode == 1) return ((const int*)p)[i] != 0;
    return ((const float*)p)[i] != 0.0f;
}

// ---------------- fp32 -> split bf16 helpers ----------------
__device__ __forceinline__ void split8(float4 a, float4 b, uint4& h, uint4& l) {
    float x[8] = {a.x, a.y, a.z, a.w, b.x, b.y, b.z, b.w};
    uint32_t hw[4], lw[4];
#pragma unroll
    for (int p = 0; p < 4; p++) {
        __nv_bfloat16 h0 = __float2bfloat16(x[2 * p]);
        __nv_bfloat16 h1 = __float2bfloat16(x[2 * p + 1]);
        __nv_bfloat16 l0 = __float2bfloat16(x[2 * p] - __bfloat162float(h0));
        __nv_bfloat16 l1 = __float2bfloat16(x[2 * p + 1] - __bfloat162float(h1));
        hw[p] = ((uint32_t)__bfloat16_as_ushort(h1) << 16) | __bfloat16_as_ushort(h0);
        lw[p] = ((uint32_t)__bfloat16_as_ushort(l1) << 16) | __bfloat16_as_ushort(l0);
    }
    h = make_uint4(hw[0], hw[1], hw[2], hw[3]);
    l = make_uint4(lw[0], lw[1], lw[2], lw[3]);
}

__device__ __forceinline__ void split4(float4 a, uint2& h, uint2& l) {
    float x[4] = {a.x, a.y, a.z, a.w};
    uint32_t hw[2], lw[2];
#pragma unroll
    for (int p = 0; p < 2; p++) {
        __nv_bfloat16 h0 = __float2bfloat16(x[2 * p]);
        __nv_bfloat16 h1 = __float2bfloat16(x[2 * p + 1]);
        __nv_bfloat16 l0 = __float2bfloat16(x[2 * p] - __bfloat162float(h0));
        __nv_bfloat16 l1 = __float2bfloat16(x[2 * p + 1] - __bfloat162float(h1));
        hw[p] = ((uint32_t)__bfloat16_as_ushort(h1) << 16) | __bfloat16_as_ushort(h0);
        lw[p] = ((uint32_t)__bfloat16_as_ushort(l1) << 16) | __bfloat16_as_ushort(l0);
    }
    h = make_uint2(hw[0], hw[1]);
    l = make_uint2(lw[0], lw[1]);
}

// split weights (row-major, stride 256)
__global__ void split_kernel(const float* __restrict__ src,
                             __nv_bfloat16* __restrict__ hi,
                             __nv_bfloat16* __restrict__ lo, int rows) {
    int r = blockIdx.x * 4 + (threadIdx.x >> 8);
    int c = threadIdx.x & 255;
    if (r >= rows) return;
    float x = src[(size_t)r * 256 + c];
    __nv_bfloat16 h = __float2bfloat16(x);
    hi[(size_t)r * 256 + c] = h;
    lo[(size_t)r * 256 + c] = __float2bfloat16(x - __bfloat162float(h));
}

// WqT[i][o] = Wq[o][i], split
__global__ void wq_prep(const float* __restrict__ Wq) {
    int i = blockIdx.x * 4 + (threadIdx.x >> 8);
    int o = threadIdx.x & 255;
    float x = Wq[(size_t)o * 256 + i];
    __nv_bfloat16 h = __float2bfloat16(x);
    g_WqTh[(size_t)i * 256 + o] = h;
    g_WqTl[(size_t)i * 256 + o] = __float2bfloat16(x - __bfloat162float(h));
}

#define MMA_OP(d, a, b) asm volatile( \
    "mma.sync.aligned.m16n8k16.row.col.f32.bf16.bf16.f32 " \
    "{%0,%1,%2,%3}, {%4,%5,%6,%7}, {%8,%9}, {%0,%1,%2,%3};\n" \
    : "+f"(d[0]), "+f"(d[1]), "+f"(d[2]), "+f"(d[3]) \
    : "r"(a[0]), "r"(a[1]), "r"(a[2]), "r"(a[3]), "r"(b[0]), "r"(b[1]))

// ---------------- dense GEMM: C = A(fp32, split in-kernel) @ W^T(pre-split) ----
__global__ __launch_bounds__(256) void gemm_f32s(
    const float* __restrict__ A, long lda, const int* __restrict__ gather,
    const __nv_bfloat16* __restrict__ Bh, const __nv_bfloat16* __restrict__ Bl,
    float* __restrict__ C, int M) {
    __shared__ __nv_bfloat16 sAh[128][40], sAl[128][40];
    __shared__ __nv_bfloat16 sBh[64][40], sBl[64][40];
    const int t = threadIdx.x, lane = t & 31, w = t >> 5;
    const int m0 = blockIdx.x * 128, n0 = blockIdx.y * 64;
    const int wr = (w & 3) * 32, wc = (w >> 2) * 32;
    float acc[2][4][4];
#pragma unroll
    for (int i = 0; i < 2; i++)
#pragma unroll
        for (int j = 0; j < 4; j++)
#pragma unroll
            for (int q = 0; q < 4; q++) acc[i][j][q] = 0.f;

    const int ar = t >> 1, ao = (t & 1) * 16;
    const int br = t >> 2, bo = (t & 3) * 8;
    const int am = m0 + ar;
    const bool aok = (am < M);
    const long asrc = aok ? (long)(gather ? gather[am] : am) : 0;
    const float* pA = A + asrc * lda + ao;
    const __nv_bfloat16* pBh = Bh + (size_t)(n0 + br) * 256 + bo;
    const __nv_bfloat16* pBl = Bl + (size_t)(n0 + br) * 256 + bo;

    for (int k0 = 0; k0 < 256; k0 += 32) {
        float4 z = make_float4(0, 0, 0, 0);
        float4 a0 = aok ? *(const float4*)(pA + k0)      : z;
        float4 a1 = aok ? *(const float4*)(pA + k0 + 4)  : z;
        float4 a2 = aok ? *(const float4*)(pA + k0 + 8)  : z;
        float4 a3 = aok ? *(const float4*)(pA + k0 + 12) : z;
        uint4 h0, l0, h1, l1;
        split8(a0, a1, h0, l0);
        split8(a2, a3, h1, l1);
        *(uint4*)&sAh[ar][ao]     = h0;
        *(uint4*)&sAh[ar][ao + 8] = h1;
        *(uint4*)&sAl[ar][ao]     = l0;
        *(uint4*)&sAl[ar][ao + 8] = l1;
        *(uint4*)&sBh[br][bo] = *(const uint4*)(pBh + k0);
        *(uint4*)&sBl[br][bo] = *(const uint4*)(pBl + k0);
        __syncthreads();
#pragma unroll
        for (int kk = 0; kk < 32; kk += 16) {
            uint32_t afh[2][4], afl[2][4], bfh[4][2], bfl[4][2];
            const int arow = wr + (lane >> 2);
            const int acol = kk + (lane & 3) * 2;
#pragma unroll
            for (int mt = 0; mt < 2; mt++) {
                const int r0 = arow + mt * 16;
                afh[mt][0] = *(const uint32_t*)&sAh[r0][acol];
                afh[mt][1] = *(const uint32_t*)&sAh[r0 + 8][acol];
                afh[mt][2] = *(const uint32_t*)&sAh[r0][acol + 8];
                afh[mt][3] = *(const uint32_t*)&sAh[r0 + 8][acol + 8];
                afl[mt][0] = *(const uint32_t*)&sAl[r0][acol];
                afl[mt][1] = *(const uint32_t*)&sAl[r0 + 8][acol];
                afl[mt][2] = *(const uint32_t*)&sAl[r0][acol + 8];
                afl[mt][3] = *(const uint32_t*)&sAl[r0 + 8][acol + 8];
            }
#pragma unroll
            for (int nt = 0; nt < 4; nt++) {
                const int nr = wc + nt * 8 + (lane >> 2);
                bfh[nt][0] = *(const uint32_t*)&sBh[nr][acol];
                bfh[nt][1] = *(const uint32_t*)&sBh[nr][acol + 8];
                bfl[nt][0] = *(const uint32_t*)&sBl[nr][acol];
                bfl[nt][1] = *(const uint32_t*)&sBl[nr][acol + 8];
            }
#pragma unroll
            for (int mt = 0; mt < 2; mt++)
#pragma unroll
                for (int nt = 0; nt < 4; nt++) {
                    MMA_OP(acc[mt][nt], afh[mt], bfh[nt]);
                    MMA_OP(acc[mt][nt], afh[mt], bfl[nt]);
                    MMA_OP(acc[mt][nt], afl[mt], bfh[nt]);
                }
        }
        __syncthreads();
    }
    const int grp = lane >> 2, qc = (lane & 3) * 2;
#pragma unroll
    for (int mt = 0; mt < 2; mt++)
#pragma unroll
        for (int nt = 0; nt < 4; nt++) {
            const int rg = m0 + wr + mt * 16 + grp;
            const int cg = n0 + wc + nt * 8 + qc;
            if (rg < M)
                *(float2*)&C[(size_t)rg * 256 + cg] =
                    make_float2(acc[mt][nt][0], acc[mt][nt][1]);
            if (rg + 8 < M)
                *(float2*)&C[(size_t)(rg + 8) * 256 + cg] =
                    make_float2(acc[mt][nt][2], acc[mt][nt][3]);
        }
}

// ---------------- u via tensor cores ----------------
__global__ __launch_bounds__(256) void u_tc(int M) {
    __shared__ __nv_bfloat16 sAh[128][40], sAl[128][40];
    __shared__ __nv_bfloat16 sBh[64][40], sBl[64][40];
    const int t = threadIdx.x, lane = t & 31, w = t >> 5;
    const int m0 = blockIdx.x * 128, i0 = blockIdx.y * 64, h = blockIdx.z;
    const int wr = (w & 3) * 32, wc = (w >> 2) * 32;
    float acc[2][4][4];
#pragma unroll
    for (int i = 0; i < 2; i++)
#pragma unroll
        for (int j = 0; j < 4; j++)
#pragma unroll
            for (int q = 0; q < 4; q++) acc[i][j][q] = 0.f;

    const int ar = t >> 1, ao = (t & 1) * 16;
    const int br = t >> 2, bo = (t & 3) * 8;
    const int am = m0 + ar;
    const bool aok = (am < M);
    {
        float4 z = make_float4(0, 0, 0, 0);
        const float* pA = g_K + (size_t)(aok ? am : 0) * 256 + h * 32 + ao;
        float4 a0 = aok ? *(const float4*)(pA)      : z;
        float4 a1 = aok ? *(const float4*)(pA + 4)  : z;
        float4 a2 = aok ? *(const float4*)(pA + 8)  : z;
        float4 a3 = aok ? *(const float4*)(pA + 12) : z;
        uint4 h0, l0, h1, l1;
        split8(a0, a1, h0, l0);
        split8(a2, a3, h1, l1);
        *(uint4*)&sAh[ar][ao]     = h0;
        *(uint4*)&sAh[ar][ao + 8] = h1;
        *(uint4*)&sAl[ar][ao]     = l0;
        *(uint4*)&sAl[ar][ao + 8] = l1;
        *(uint4*)&sBh[br][bo] = *(const uint4*)&g_WqTh[(size_t)(i0 + br) * 256 + h * 32 + bo];
        *(uint4*)&sBl[br][bo] = *(const uint4*)&g_WqTl[(size_t)(i0 + br) * 256 + h * 32 + bo];
    }
    __syncthreads();
#pragma unroll
    for (int kk = 0; kk < 32; kk += 16) {
        uint32_t afh[2][4], afl[2][4], bfh[4][2], bfl[4][2];
        const int arow = wr + (lane >> 2);
        const int acol = kk + (lane & 3) * 2;
#pragma unroll
        for (int mt = 0; mt < 2; mt++) {
            const int r0 = arow + mt * 16;
            afh[mt][0] = *(const uint32_t*)&sAh[r0][acol];
            afh[mt][1] = *(const uint32_t*)&sAh[r0 + 8][acol];
            afh[mt][2] = *(const uint32_t*)&sAh[r0][acol + 8];
            afh[mt][3] = *(const uint32_t*)&sAh[r0 + 8][acol + 8];
            afl[mt][0] = *(const uint32_t*)&sAl[r0][acol];
            afl[mt][1] = *(const uint32_t*)&sAl[r0 + 8][acol];
            afl[mt][2] = *(const uint32_t*)&sAl[r0][acol + 8];
            afl[mt][3] = *(const uint32_t*)&sAl[r0 + 8][acol + 8];
        }
#pragma unroll
        for (int nt = 0; nt < 4; nt++) {
            const int nr = wc + nt * 8 + (lane >> 2);
            bfh[nt][0] = *(const uint32_t*)&sBh[nr][acol];
            bfh[nt][1] = *(const uint32_t*)&sBh[nr][acol + 8];
            bfl[nt][0] = *(const uint32_t*)&sBl[nr][acol];
            bfl[nt][1] = *(const uint32_t*)&sBl[nr][acol + 8];
        }
#pragma unroll
        for (int mt = 0; mt < 2; mt++)
#pragma unroll
            for (int nt = 0; nt < 4; nt++) {
                MMA_OP(acc[mt][nt], afh[mt], bfh[nt]);
                MMA_OP(acc[mt][nt], afh[mt], bfl[nt]);
                MMA_OP(acc[mt][nt], afl[mt], bfh[nt]);
            }
    }
    const int grp = lane >> 2, qc = (lane & 3) * 2;
#pragma unroll
    for (int mt = 0; mt < 2; mt++)
#pragma unroll
        for (int nt = 0; nt < 4; nt++) {
            const int rg = m0 + wr + mt * 16 + grp;
            const int cg = h * 256 + i0 + wc + nt * 8 + qc;
            if (rg < M)
                *(float2*)&g_U[(size_t)rg * 2048 + cg] =
                    make_float2(acc[mt][nt][0], acc[mt][nt][1]);
            if (rg + 8 < M)
                *(float2*)&g_U[(size_t)(rg + 8) * 2048 + cg] =
                    make_float2(acc[mt][nt][2], acc[mt][nt][3]);
        }
}

// ---------------- vproj via tensor cores ----------------
__global__ __launch_bounds__(256) void vproj_tc(const float* __restrict__ Wv, int M) {
    __shared__ __nv_bfloat16 sAh[128][40], sAl[128][40];
    __shared__ __nv_bfloat16 sBh[32][40], sBl[32][40];
    const int t = threadIdx.x, lane = t & 31, w = t >> 5;
    const int m0 = blockIdx.x * 128, h = blockIdx.y;
    const int wr = (w & 3) * 32, wc = (w >> 2) * 16;
    float acc[2][2][4];
#pragma unroll
    for (int i = 0; i < 2; i++)
#pragma unroll
        for (int j = 0; j < 2; j++)
#pragma unroll
            for (int q = 0; q < 4; q++) acc[i][j][q] = 0.f;

    const int ar = t >> 1, ao = (t & 1) * 16;
    const int br = t >> 3, bo = (t & 7) * 4;
    const int am = m0 + ar;
    const bool aok = (am < M);
    const float* pA = g_A + (size_t)(aok ? am : 0) * 2048 + h * 256 + ao;
    const float* pB = Wv + (size_t)(h * 32 + br) * 256 + bo;

    for (int k0 = 0; k0 < 256; k0 += 32) {
        float4 z = make_float4(0, 0, 0, 0);
        float4 a0 = aok ? *(const float4*)(pA + k0)      : z;
        float4 a1 = aok ? *(const float4*)(pA + k0 + 4)  : z;
        float4 a2 = aok ? *(const float4*)(pA + k0 + 8)  : z;
        float4 a3 = aok ? *(const float4*)(pA + k0 + 12) : z;
        uint4 h0, l0, h1, l1;
        split8(a0, a1, h0, l0);
        split8(a2, a3, h1, l1);
        *(uint4*)&sAh[ar][ao]     = h0;
        *(uint4*)&sAh[ar][ao + 8] = h1;
        *(uint4*)&sAl[ar][ao]     = l0;
        *(uint4*)&sAl[ar][ao + 8] = l1;
        float4 bv = *(const float4*)(pB + k0);
        uint2 bh, bl;
        split4(bv, bh, bl);
        *(uint2*)&sBh[br][bo] = bh;
        *(uint2*)&sBl[br][bo] = bl;
        __syncthreads();
#pragma unroll
        for (int kk = 0; kk < 32; kk += 16) {
            uint32_t afh[2][4], afl[2][4], bfh[2][2], bfl[2][2];
            const int arow = wr + (lane >> 2);
            const int acol = kk + (lane & 3) * 2;
#pragma unroll
            for (int mt = 0; mt < 2; mt++) {
                const int r0 = arow + mt * 16;
                afh[mt][0] = *(const uint32_t*)&sAh[r0][acol];
                afh[mt][1] = *(const uint32_t*)&sAh[r0 + 8][acol];
                afh[mt][2] = *(const uint32_t*)&sAh[r0][acol + 8];
                afh[mt][3] = *(const uint32_t*)&sAh[r0 + 8][acol + 8];
                afl[mt][0] = *(const uint32_t*)&sAl[r0][acol];
                afl[mt][1] = *(const uint32_t*)&sAl[r0 + 8][acol];
                afl[mt][2] = *(const uint32_t*)&sAl[r0][acol + 8];
                afl[mt][3] = *(const uint32_t*)&sAl[r0 + 8][acol + 8];
            }
#pragma unroll
            for (int nt = 0; nt < 2; nt++) {
                const int nr = wc + nt * 8 + (lane >> 2);
                bfh[nt][0] = *(const uint32_t*)&sBh[nr][acol];
                bfh[nt][1] = *(const uint32_t*)&sBh[nr][acol + 8];
                bfl[nt][0] = *(const uint32_t*)&sBl[nr][acol];
                bfl[nt][1] = *(const uint32_t*)&sBl[nr][acol + 8];
            }
#pragma unroll
            for (int mt = 0; mt < 2; mt++)
#pragma unroll
                for (int nt = 0; nt < 2; nt++) {
                    MMA_OP(acc[mt][nt], afh[mt], bfh[nt]);
                    MMA_OP(acc[mt][nt], afh[mt], bfl[nt]);
                    MMA_OP(acc[mt][nt], afl[mt], bfh[nt]);
                }
        }
        __syncthreads();
    }
    const int grp = lane >> 2, qc = (lane & 3) * 2;
#pragma unroll
    for (int mt = 0; mt < 2; mt++)
#pragma unroll
        for (int nt = 0; nt < 2; nt++) {
            const int rg = m0 + wr + mt * 16 + grp;
            const int cg = h * 32 + wc + nt * 8 + qc;
            if (rg < M)
                *(float2*)&g_V[(size_t)rg * 256 + cg] =
                    make_float2(acc[mt][nt][0], acc[mt][nt][1]);
            if (rg + 8 < M)
                *(float2*)&g_V[(size_t)(rg + 8) * 256 + cg] =
                    make_float2(acc[mt][nt][2], acc[mt][nt][3]);
        }
}

// ---------------- attention: warp-per-node, no block syncs ----------------
// lane owns d = j*32+lane (j=0..7). Score reduce = folding butterfly (9 shfl).
// After fold: lane holds head myh = bit4<<2 | bit3<<1 | bit2 of lane.
__global__ __launch_bounds__(128) void attn_fused(
        const float* __restrict__ ccw, const float* __restrict__ cw,
        const void* __restrict__ ccwm, const void* __restrict__ cwm, int N) {
    __shared__ float p_sm[4][8][20];
    const int t = threadIdx.x, lane = t & 31, w = t >> 5;
    const int n = blockIdx.x * 4 + w;
    if (n >= N) return;
    const size_t nb = n;
    const int mode = g_maskMode;
    const int myh = (((lane >> 4) & 1) << 2) | (((lane >> 3) & 1) << 1) | ((lane >> 2) & 1);
    const float NEG = __int_as_float(0xff800000);
    const float SCALE = 0.17677669529663688f;

    float u[8][8];
#pragma unroll
    for (int h = 0; h < 8; h++)
#pragma unroll
        for (int j = 0; j < 8; j++)
            u[h][j] = g_U[nb * 2048 + h * 256 + j * 32 + lane];

    float sc[18];
#pragma unroll
    for (int s = 0; s < 18; s++) {
        const float* src;
        if (s < 8)       src = ccw + nb * 2048 + (size_t)s * 256;
        else if (s == 8) src = g_S + nb * 256;
        else if (s == 9) src = g_P + nb * 256;
        else             src = cw + nb * 2048 + (size_t)(s - 10) * 256;
        float m[8];
#pragma unroll
        for (int j = 0; j < 8; j++) m[j] = src[j * 32 + lane];
        float part[8];
#pragma unroll
        for (int h = 0; h < 8; h++) {
            float p = 0.f;
#pragma unroll
            for (int j = 0; j < 8; j++) p += m[j] * u[h][j];
            part[h] = p;
        }
        // fold 8 values -> 1 per lane, head index = lane bits [4:2]
#pragma unroll
        for (int i = 0; i < 4; i++) {
            float a = part[i], b = part[i + 4];
            float send = (lane & 16) ? a : b;
            float recv = __shfl_xor_sync(0xFFFFFFFFu, send, 16);
            part[i] = ((lane & 16) ? b : a) + recv;
        }
#pragma unroll
        for (int i = 0; i < 2; i++) {
            float a = part[i], b = part[i + 2];
            float send = (lane & 8) ? a : b;
            float recv = __shfl_xor_sync(0xFFFFFFFFu, send, 8);
            part[i] = ((lane & 8) ? b : a) + recv;
        }
        {
            float a = part[0], b = part[1];
            float send = (lane & 4) ? a : b;
            float recv = __shfl_xor_sync(0xFFFFFFFFu, send, 4);
            part[0] = ((lane & 4) ? b : a) + recv;
        }
        part[0] += __shfl_xor_sync(0xFFFFFFFFu, part[0], 2);
        part[0] += __shfl_xor_sync(0xFFFFFFFFu, part[0], 1);
        sc[s] = part[0];
    }

    // in-register masked softmax over 18 slots (head = myh)
    unsigned vb = 3u << 8;
#pragma unroll
    for (int s = 0; s < 8; s++)
        if (mask_at(ccwm, n * 8 + s, mode)) vb |= 1u << s;
#pragma unroll
    for (int s = 0; s < 8; s++)
        if (mask_at(cwm, n * 8 + s, mode)) vb |= 1u << (10 + s);
    float mx = NEG;
#pragma unroll
    for (int s = 0; s < 18; s++)
        if ((vb >> s) & 1) mx = fmaxf(mx, sc[s] * SCALE);
    float sum = 0.f;
    float pr[18];
#pragma unroll
    for (int s = 0; s < 18; s++) {
        float e = ((vb >> s) & 1) ? __expf(sc[s] * SCALE - mx) : 0.f;
        pr[s] = e;
        sum += e;
    }
    const float inv = 1.f / sum;
    if ((lane & 3) == 0) {
#pragma unroll
        for (int s = 0; s < 18; s++) p_sm[w][myh][s] = pr[s] * inv;
    }
    __syncwarp();

    // aggregate: acc[h][j] over slots, p from smem broadcast
    float acc[8][8];
#pragma unroll
    for (int h = 0; h < 8; h++)
#pragma unroll
        for (int j = 0; j < 8; j++) acc[h][j] = 0.f;
#pragma unroll
    for (int s = 0; s < 18; s++) {
        const float* src;
        if (s < 8)       src = ccw + nb * 2048 + (size_t)s * 256;
        else if (s == 8) src = g_S + nb * 256;
        else if (s == 9) src = g_P + nb * 256;
        else             src = cw + nb * 2048 + (size_t)(s - 10) * 256;
        float m[8];
#pragma unroll
        for (int j = 0; j < 8; j++) m[j] = src[j * 32 + lane];
#pragma unroll
        for (int h = 0; h < 8; h++) {
            float ph = p_sm[w][h][s];
#pragma unroll
            for (int j = 0; j < 8; j++) acc[h][j] += ph * m[j];
        }
    }
#pragma unroll
    for (int h = 0; h < 8; h++)
#pragma unroll
        for (int j = 0; j < 8; j++)
            g_A[nb * 2048 + h * 256 + j * 32 + lane] = acc[h][j];
}

extern "C" void kernel_launch(void* const* d_in, const int* in_sizes, int n_in,
                              void* d_out, int out_size) {
    const float* X    = (const float*)d_in[0];
    const int*   pidx = (const int*)d_in[1];
    const float* ccw  = (const float*)d_in[2];
    const void*  ccwm = d_in[3];
    const float* cw   = (const float*)d_in[4];
    const void*  cwm  = d_in[5];
    const float* Wself = (const float*)d_in[6];
    const float* Wpar  = (const float*)d_in[7];
    const float* Wq    = (const float*)d_in[8];
    const float* Wk    = (const float*)d_in[9];
    const float* Wv    = (const float*)d_in[10];
    const float* Wfin  = (const float*)d_in[11];
    float* out = (float*)d_out;
    const int N = in_sizes[0] / 256;

    float *pS, *pP, *pK, *pV;
    __nv_bfloat16 *pWh, *pWl;
    cudaGetSymbolAddress((void**)&pS, g_S);
    cudaGetSymbolAddress((void**)&pP, g_P);
    cudaGetSymbolAddress((void**)&pK, g_K);
    cudaGetSymbolAddress((void**)&pV, g_V);
    cudaGetSymbolAddress((void**)&pWh, g_Wh);
    cudaGetSymbolAddress((void**)&pWl, g_Wl);

    detect_kernel<<<1, 256>>>((const unsigned char*)ccwm, in_sizes[3]);

    const int WSZ = 256 * 256;
    split_kernel<<<64, 1024>>>(Wself, pWh + 0 * WSZ, pWl + 0 * WSZ, 256);
    split_kernel<<<64, 1024>>>(Wpar,  pWh + 1 * WSZ, pWl + 1 * WSZ, 256);
    split_kernel<<<64, 1024>>>(Wk,    pWh + 2 * WSZ, pWl + 2 * WSZ, 256);
    split_kernel<<<64, 1024>>>(Wfin,  pWh + 3 * WSZ, pWl + 3 * WSZ, 256);
    wq_prep<<<64, 1024>>>(Wq);

    dim3 gg((N + 127) / 128, 4);
    gemm_f32s<<<gg, 256>>>(X,   256,  nullptr, pWh + 0 * WSZ, pWl + 0 * WSZ, pS, N);
    gemm_f32s<<<gg, 256>>>(X,   256,  pidx,    pWh + 1 * WSZ, pWl + 1 * WSZ, pP, N);
    gemm_f32s<<<gg, 256>>>(ccw, 2048, nullptr, pWh + 2 * WSZ, pWl + 2 * WSZ, pK, N);

    u_tc<<<dim3((N + 127) / 128, 4, 8), 256>>>(N);
    attn_fused<<<(N + 3) / 4, 128>>>(ccw, cw, ccwm, cwm, N);
    vproj_tc<<<dim3((N + 127) / 128, 8), 256>>>(Wv, N);

    gemm_f32s<<<gg, 256>>>(pV, 256, nullptr, pWh + 3 * WSZ, pWl + 3 * WSZ, out, N);
}

// round 7
// speedup vs baseline: 1.9363x; 1.1146x over previous
#include <cuda_runtime.h>
#include <cuda_bf16.h>
#include <cuda_fp16.h>
#include <cstdint>
#include <cstddef>

#define MAXN 30000

__device__ float g_K[(size_t)MAXN * 256];
__device__ float g_V[(size_t)MAXN * 256];
__device__ float g_SP[(size_t)MAXN * 512];
__device__ float g_U[(size_t)MAXN * 8 * 256];
__device__ float g_A[(size_t)MAXN * 8 * 256];
__device__ __nv_bfloat16 g_Wkh[256 * 256], g_Wkl[256 * 256];
__device__ __nv_bfloat16 g_WqTh[256 * 256], g_WqTl[256 * 256];
__device__ __half g_WspH[512 * 256];
__device__ __half g_WfinH[256 * 256];
__device__ __half g_WvH[256 * 256];
__device__ int g_maskMode;

// ---------------- mask dtype detection (deterministic) ----------------
__global__ void detect_kernel(const unsigned char* __restrict__ m, int nelem) {
    __shared__ int s_nzoff, s_badf, s_anyf;
    if (threadIdx.x == 0) { s_nzoff = 0; s_badf = 0; s_anyf = 0; }
    __syncthreads();
    int words = min(nelem / 4, 1024);
    const unsigned int* wm = (const unsigned int*)m;
    int nz = 0, bf = 0, af = 0;
    for (int i = threadIdx.x; i < words; i += blockDim.x) {
        unsigned int w = wm[i];
        if (w >> 8) nz = 1;
        if (w != 0u && w != 0x3F800000u) bf = 1;
        if (w == 0x3F800000u) af = 1;
    }
    if (nz) atomicOr(&s_nzoff, 1);
    if (bf) atomicOr(&s_badf, 1);
    if (af) atomicOr(&s_anyf, 1);
    __syncthreads();
    if (threadIdx.x == 0)
        g_maskMode = (!s_badf && s_anyf) ? 2 : (!s_nzoff ? 1 : 0);
}

__device__ __forceinline__ bool mask_at(const void* p, int i, int mode) {
    if (mode == 0) return ((const unsigned char*)p)[i] != 0;
    if (mode == 1) return ((const int*)p)[i] != 0;
    return ((const float*)p)[i] != 0.0f;
}

// ---------------- weight prep: one kernel, 6 jobs ----------------
// job 0: Wself -> WspH rows 0..255   (fp16)
// job 1: Wpar  -> WspH rows 256..511 (fp16)
// job 2: Wfin  -> WfinH              (fp16)
// job 3: Wv    -> WvH                (fp16)
// job 4: Wk    -> Wkh/Wkl            (split bf16)
// job 5: Wq    -> WqTh/WqTl          (transposed, split bf16)
__global__ void prep_weights(const float* __restrict__ Wself, const float* __restrict__ Wpar,
                             const float* __restrict__ Wfin, const float* __restrict__ Wv,
                             const float* __restrict__ Wk, const float* __restrict__ Wq) {
    int r = blockIdx.x * 4 + (threadIdx.x >> 8);
    int c = threadIdx.x & 255;
    int job = blockIdx.y;
    size_t idx = (size_t)r * 256 + c;
    switch (job) {
        case 0: g_WspH[idx] = __float2half_rn(Wself[idx]); break;
        case 1: g_WspH[idx + 256 * 256] = __float2half_rn(Wpar[idx]); break;
        case 2: g_WfinH[idx] = __float2half_rn(Wfin[idx]); break;
        case 3: g_WvH[idx] = __float2half_rn(Wv[idx]); break;
        case 4: {
            float x = Wk[idx];
            __nv_bfloat16 h = __float2bfloat16(x);
            g_Wkh[idx] = h;
            g_Wkl[idx] = __float2bfloat16(x - __bfloat162float(h));
            break;
        }
        case 5: {
            float x = Wq[(size_t)c * 256 + r];  // transpose
            __nv_bfloat16 h = __float2bfloat16(x);
            g_WqTh[idx] = h;
            g_WqTl[idx] = __float2bfloat16(x - __bfloat162float(h));
            break;
        }
    }
}

// ---------------- fp32 -> split bf16 helper ----------------
__device__ __forceinline__ void split8(float4 a, float4 b, uint4& h, uint4& l) {
    float x[8] = {a.x, a.y, a.z, a.w, b.x, b.y, b.z, b.w};
    uint32_t hw[4], lw[4];
#pragma unroll
    for (int p = 0; p < 4; p++) {
        __nv_bfloat16 h0 = __float2bfloat16(x[2 * p]);
        __nv_bfloat16 h1 = __float2bfloat16(x[2 * p + 1]);
        __nv_bfloat16 l0 = __float2bfloat16(x[2 * p] - __bfloat162float(h0));
        __nv_bfloat16 l1 = __float2bfloat16(x[2 * p + 1] - __bfloat162float(h1));
        hw[p] = ((uint32_t)__bfloat16_as_ushort(h1) << 16) | __bfloat16_as_ushort(h0);
        lw[p] = ((uint32_t)__bfloat16_as_ushort(l1) << 16) | __bfloat16_as_ushort(l0);
    }
    h = make_uint4(hw[0], hw[1], hw[2], hw[3]);
    l = make_uint4(lw[0], lw[1], lw[2], lw[3]);
}

__device__ __forceinline__ uint4 cvt8_f16(float4 a, float4 b) {
    uint32_t w[4];
    w[0] = ((uint32_t)__half_as_ushort(__float2half_rn(a.y)) << 16) | __half_as_ushort(__float2half_rn(a.x));
    w[1] = ((uint32_t)__half_as_ushort(__float2half_rn(a.w)) << 16) | __half_as_ushort(__float2half_rn(a.z));
    w[2] = ((uint32_t)__half_as_ushort(__float2half_rn(b.y)) << 16) | __half_as_ushort(__float2half_rn(b.x));
    w[3] = ((uint32_t)__half_as_ushort(__float2half_rn(b.w)) << 16) | __half_as_ushort(__float2half_rn(b.z));
    return make_uint4(w[0], w[1], w[2], w[3]);
}

#define MMA_BF16(d, a, b) asm volatile( \
    "mma.sync.aligned.m16n8k16.row.col.f32.bf16.bf16.f32 " \
    "{%0,%1,%2,%3}, {%4,%5,%6,%7}, {%8,%9}, {%0,%1,%2,%3};\n" \
    : "+f"(d[0]), "+f"(d[1]), "+f"(d[2]), "+f"(d[3]) \
    : "r"(a[0]), "r"(a[1]), "r"(a[2]), "r"(a[3]), "r"(b[0]), "r"(b[1]))

#define MMA_F16(d, a, b) asm volatile( \
    "mma.sync.aligned.m16n8k16.row.col.f32.f16.f16.f32 " \
    "{%0,%1,%2,%3}, {%4,%5,%6,%7}, {%8,%9}, {%0,%1,%2,%3};\n" \
    : "+f"(d[0]), "+f"(d[1]), "+f"(d[2]), "+f"(d[3]) \
    : "r"(a[0]), "r"(a[1]), "r"(a[2]), "r"(a[3]), "r"(b[0]), "r"(b[1]))

// ---------------- 3-split bf16 GEMM (score path): C = A @ B^T ----------------
__global__ __launch_bounds__(256) void gemm_f32s(
    const float* __restrict__ A, long lda,
    const __nv_bfloat16* __restrict__ Bh, const __nv_bfloat16* __restrict__ Bl,
    float* __restrict__ C, int M) {
    __shared__ __nv_bfloat16 sAh[128][40], sAl[128][40];
    __shared__ __nv_bfloat16 sBh[64][40], sBl[64][40];
    const int t = threadIdx.x, lane = t & 31, w = t >> 5;
    const int m0 = blockIdx.x * 128, n0 = blockIdx.y * 64;
    const int wr = (w & 3) * 32, wc = (w >> 2) * 32;
    float acc[2][4][4];
#pragma unroll
    for (int i = 0; i < 2; i++)
#pragma unroll
        for (int j = 0; j < 4; j++)
#pragma unroll
            for (int q = 0; q < 4; q++) acc[i][j][q] = 0.f;

    const int ar = t >> 1, ao = (t & 1) * 16;
    const int br = t >> 2, bo = (t & 3) * 8;
    const int am = m0 + ar;
    const bool aok = (am < M);
    const float* pA = A + (size_t)(aok ? am : 0) * lda + ao;
    const __nv_bfloat16* pBh = Bh + (size_t)(n0 + br) * 256 + bo;
    const __nv_bfloat16* pBl = Bl + (size_t)(n0 + br) * 256 + bo;

    for (int k0 = 0; k0 < 256; k0 += 32) {
        float4 z = make_float4(0, 0, 0, 0);
        float4 a0 = aok ? *(const float4*)(pA + k0)      : z;
        float4 a1 = aok ? *(const float4*)(pA + k0 + 4)  : z;
        float4 a2 = aok ? *(const float4*)(pA + k0 + 8)  : z;
        float4 a3 = aok ? *(const float4*)(pA + k0 + 12) : z;
        uint4 h0, l0, h1, l1;
        split8(a0, a1, h0, l0);
        split8(a2, a3, h1, l1);
        *(uint4*)&sAh[ar][ao]     = h0;
        *(uint4*)&sAh[ar][ao + 8] = h1;
        *(uint4*)&sAl[ar][ao]     = l0;
        *(uint4*)&sAl[ar][ao + 8] = l1;
        *(uint4*)&sBh[br][bo] = *(const uint4*)(pBh + k0);
        *(uint4*)&sBl[br][bo] = *(const uint4*)(pBl + k0);
        __syncthreads();
#pragma unroll
        for (int kk = 0; kk < 32; kk += 16) {
            uint32_t afh[2][4], afl[2][4], bfh[4][2], bfl[4][2];
            const int arow = wr + (lane >> 2);
            const int acol = kk + (lane & 3) * 2;
#pragma unroll
            for (int mt = 0; mt < 2; mt++) {
                const int r0 = arow + mt * 16;
                afh[mt][0] = *(const uint32_t*)&sAh[r0][acol];
                afh[mt][1] = *(const uint32_t*)&sAh[r0 + 8][acol];
                afh[mt][2] = *(const uint32_t*)&sAh[r0][acol + 8];
                afh[mt][3] = *(const uint32_t*)&sAh[r0 + 8][acol + 8];
                afl[mt][0] = *(const uint32_t*)&sAl[r0][acol];
                afl[mt][1] = *(const uint32_t*)&sAl[r0 + 8][acol];
                afl[mt][2] = *(const uint32_t*)&sAl[r0][acol + 8];
                afl[mt][3] = *(const uint32_t*)&sAl[r0 + 8][acol + 8];
            }
#pragma unroll
            for (int nt = 0; nt < 4; nt++) {
                const int nr = wc + nt * 8 + (lane >> 2);
                bfh[nt][0] = *(const uint32_t*)&sBh[nr][acol];
                bfh[nt][1] = *(const uint32_t*)&sBh[nr][acol + 8];
                bfl[nt][0] = *(const uint32_t*)&sBl[nr][acol];
                bfl[nt][1] = *(const uint32_t*)&sBl[nr][acol + 8];
            }
#pragma unroll
            for (int mt = 0; mt < 2; mt++)
#pragma unroll
                for (int nt = 0; nt < 4; nt++) {
                    MMA_BF16(acc[mt][nt], afh[mt], bfh[nt]);
                    MMA_BF16(acc[mt][nt], afh[mt], bfl[nt]);
                    MMA_BF16(acc[mt][nt], afl[mt], bfh[nt]);
                }
        }
        __syncthreads();
    }
    const int grp = lane >> 2, qc = (lane & 3) * 2;
#pragma unroll
    for (int mt = 0; mt < 2; mt++)
#pragma unroll
        for (int nt = 0; nt < 4; nt++) {
            const int rg = m0 + wr + mt * 16 + grp;
            const int cg = n0 + wc + nt * 8 + qc;
            if (rg < M)
                *(float2*)&C[(size_t)rg * 256 + cg] =
                    make_float2(acc[mt][nt][0], acc[mt][nt][1]);
            if (rg + 8 < M)
                *(float2*)&C[(size_t)(rg + 8) * 256 + cg] =
                    make_float2(acc[mt][nt][2], acc[mt][nt][3]);
        }
}

// ---------------- fp16 single-product GEMM (linear paths): C = A @ B^T ------
// A fp32 (converted in-kernel), B fp16 row-major [N][256]. ldc configurable.
__global__ __launch_bounds__(256) void gemm_f16(
    const float* __restrict__ A, long lda,
    const __half* __restrict__ B,
    float* __restrict__ C, long ldc, int M) {
    __shared__ __half sA[128][40];
    __shared__ __half sB[64][40];
    const int t = threadIdx.x, lane = t & 31, w = t >> 5;
    const int m0 = blockIdx.x * 128, n0 = blockIdx.y * 64;
    const int wr = (w & 3) * 32, wc = (w >> 2) * 32;
    float acc[2][4][4];
#pragma unroll
    for (int i = 0; i < 2; i++)
#pragma unroll
        for (int j = 0; j < 4; j++)
#pragma unroll
            for (int q = 0; q < 4; q++) acc[i][j][q] = 0.f;

    const int ar = t >> 1, ao = (t & 1) * 16;
    const int br = t >> 2, bo = (t & 3) * 8;
    const int am = m0 + ar;
    const bool aok = (am < M);
    const float* pA = A + (size_t)(aok ? am : 0) * lda + ao;
    const __half* pB = B + (size_t)(n0 + br) * 256 + bo;

    for (int k0 = 0; k0 < 256; k0 += 32) {
        float4 z = make_float4(0, 0, 0, 0);
        float4 a0 = aok ? *(const float4*)(pA + k0)      : z;
        float4 a1 = aok ? *(const float4*)(pA + k0 + 4)  : z;
        float4 a2 = aok ? *(const float4*)(pA + k0 + 8)  : z;
        float4 a3 = aok ? *(const float4*)(pA + k0 + 12) : z;
        *(uint4*)&sA[ar][ao]     = cvt8_f16(a0, a1);
        *(uint4*)&sA[ar][ao + 8] = cvt8_f16(a2, a3);
        *(uint4*)&sB[br][bo] = *(const uint4*)(pB + k0);
        __syncthreads();
#pragma unroll
        for (int kk = 0; kk < 32; kk += 16) {
            uint32_t af[2][4], bf[4][2];
            const int arow = wr + (lane >> 2);
            const int acol = kk + (lane & 3) * 2;
#pragma unroll
            for (int mt = 0; mt < 2; mt++) {
                const int r0 = arow + mt * 16;
                af[mt][0] = *(const uint32_t*)&sA[r0][acol];
                af[mt][1] = *(const uint32_t*)&sA[r0 + 8][acol];
                af[mt][2] = *(const uint32_t*)&sA[r0][acol + 8];
                af[mt][3] = *(const uint32_t*)&sA[r0 + 8][acol + 8];
            }
#pragma unroll
            for (int nt = 0; nt < 4; nt++) {
                const int nr = wc + nt * 8 + (lane >> 2);
                bf[nt][0] = *(const uint32_t*)&sB[nr][acol];
                bf[nt][1] = *(const uint32_t*)&sB[nr][acol + 8];
            }
#pragma unroll
            for (int mt = 0; mt < 2; mt++)
#pragma unroll
                for (int nt = 0; nt < 4; nt++)
                    MMA_F16(acc[mt][nt], af[mt], bf[nt]);
        }
        __syncthreads();
    }
    const int grp = lane >> 2, qc = (lane & 3) * 2;
#pragma unroll
    for (int mt = 0; mt < 2; mt++)
#pragma unroll
        for (int nt = 0; nt < 4; nt++) {
            const int rg = m0 + wr + mt * 16 + grp;
            const int cg = n0 + wc + nt * 8 + qc;
            if (rg < M)
                *(float2*)&C[(size_t)rg * ldc + cg] =
                    make_float2(acc[mt][nt][0], acc[mt][nt][1]);
            if (rg + 8 < M)
                *(float2*)&C[(size_t)(rg + 8) * ldc + cg] =
                    make_float2(acc[mt][nt][2], acc[mt][nt][3]);
        }
}

// ---------------- u via tensor cores (3-split bf16, score path) ----------------
__global__ __launch_bounds__(256) void u_tc(int M) {
    __shared__ __nv_bfloat16 sAh[128][40], sAl[128][40];
    __shared__ __nv_bfloat16 sBh[64][40], sBl[64][40];
    const int t = threadIdx.x, lane = t & 31, w = t >> 5;
    const int m0 = blockIdx.x * 128, i0 = blockIdx.y * 64, h = blockIdx.z;
    const int wr = (w & 3) * 32, wc = (w >> 2) * 32;
    float acc[2][4][4];
#pragma unroll
    for (int i = 0; i < 2; i++)
#pragma unroll
        for (int j = 0; j < 4; j++)
#pragma unroll
            for (int q = 0; q < 4; q++) acc[i][j][q] = 0.f;

    const int ar = t >> 1, ao = (t & 1) * 16;
    const int br = t >> 2, bo = (t & 3) * 8;
    const int am = m0 + ar;
    const bool aok = (am < M);
    {
        float4 z = make_float4(0, 0, 0, 0);
        const float* pA = g_K + (size_t)(aok ? am : 0) * 256 + h * 32 + ao;
        float4 a0 = aok ? *(const float4*)(pA)      : z;
        float4 a1 = aok ? *(const float4*)(pA + 4)  : z;
        float4 a2 = aok ? *(const float4*)(pA + 8)  : z;
        float4 a3 = aok ? *(const float4*)(pA + 12) : z;
        uint4 h0, l0, h1, l1;
        split8(a0, a1, h0, l0);
        split8(a2, a3, h1, l1);
        *(uint4*)&sAh[ar][ao]     = h0;
        *(uint4*)&sAh[ar][ao + 8] = h1;
        *(uint4*)&sAl[ar][ao]     = l0;
        *(uint4*)&sAl[ar][ao + 8] = l1;
        *(uint4*)&sBh[br][bo] = *(const uint4*)&g_WqTh[(size_t)(i0 + br) * 256 + h * 32 + bo];
        *(uint4*)&sBl[br][bo] = *(const uint4*)&g_WqTl[(size_t)(i0 + br) * 256 + h * 32 + bo];
    }
    __syncthreads();
#pragma unroll
    for (int kk = 0; kk < 32; kk += 16) {
        uint32_t afh[2][4], afl[2][4], bfh[4][2], bfl[4][2];
        const int arow = wr + (lane >> 2);
        const int acol = kk + (lane & 3) * 2;
#pragma unroll
        for (int mt = 0; mt < 2; mt++) {
            const int r0 = arow + mt * 16;
            afh[mt][0] = *(const uint32_t*)&sAh[r0][acol];
            afh[mt][1] = *(const uint32_t*)&sAh[r0 + 8][acol];
            afh[mt][2] = *(const uint32_t*)&sAh[r0][acol + 8];
            afh[mt][3] = *(const uint32_t*)&sAh[r0 + 8][acol + 8];
            afl[mt][0] = *(const uint32_t*)&sAl[r0][acol];
            afl[mt][1] = *(const uint32_t*)&sAl[r0 + 8][acol];
            afl[mt][2] = *(const uint32_t*)&sAl[r0][acol + 8];
            afl[mt][3] = *(const uint32_t*)&sAl[r0 + 8][acol + 8];
        }
#pragma unroll
        for (int nt = 0; nt < 4; nt++) {
            const int nr = wc + nt * 8 + (lane >> 2);
            bfh[nt][0] = *(const uint32_t*)&sBh[nr][acol];
            bfh[nt][1] = *(const uint32_t*)&sBh[nr][acol + 8];
            bfl[nt][0] = *(const uint32_t*)&sBl[nr][acol];
            bfl[nt][1] = *(const uint32_t*)&sBl[nr][acol + 8];
        }
#pragma unroll
        for (int mt = 0; mt < 2; mt++)
#pragma unroll
            for (int nt = 0; nt < 4; nt++) {
                MMA_BF16(acc[mt][nt], afh[mt], bfh[nt]);
                MMA_BF16(acc[mt][nt], afh[mt], bfl[nt]);
                MMA_BF16(acc[mt][nt], afl[mt], bfh[nt]);
            }
    }
    const int grp = lane >> 2, qc = (lane & 3) * 2;
#pragma unroll
    for (int mt = 0; mt < 2; mt++)
#pragma unroll
        for (int nt = 0; nt < 4; nt++) {
            const int rg = m0 + wr + mt * 16 + grp;
            const int cg = h * 256 + i0 + wc + nt * 8 + qc;
            if (rg < M)
                *(float2*)&g_U[(size_t)rg * 2048 + cg] =
                    make_float2(acc[mt][nt][0], acc[mt][nt][1]);
            if (rg + 8 < M)
                *(float2*)&g_U[(size_t)(rg + 8) * 2048 + cg] =
                    make_float2(acc[mt][nt][2], acc[mt][nt][3]);
        }
}

// ---------------- vproj via fp16 tensor cores ----------------
__global__ __launch_bounds__(256) void vproj_f16(int M) {
    __shared__ __half sA[128][40];
    __shared__ __half sB[32][40];
    const int t = threadIdx.x, lane = t & 31, w = t >> 5;
    const int m0 = blockIdx.x * 128, h = blockIdx.y;
    const int wr = (w & 3) * 32, wc = (w >> 2) * 16;
    float acc[2][2][4];
#pragma unroll
    for (int i = 0; i < 2; i++)
#pragma unroll
        for (int j = 0; j < 2; j++)
#pragma unroll
            for (int q = 0; q < 4; q++) acc[i][j][q] = 0.f;

    const int ar = t >> 1, ao = (t & 1) * 16;
    const int br = t >> 3, bo = (t & 7) * 4;
    const int am = m0 + ar;
    const bool aok = (am < M);
    const float* pA = g_A + (size_t)(aok ? am : 0) * 2048 + h * 256 + ao;
    const __half* pB = g_WvH + (size_t)(h * 32 + br) * 256 + bo;

    for (int k0 = 0; k0 < 256; k0 += 32) {
        float4 z = make_float4(0, 0, 0, 0);
        float4 a0 = aok ? *(const float4*)(pA + k0)      : z;
        float4 a1 = aok ? *(const float4*)(pA + k0 + 4)  : z;
        float4 a2 = aok ? *(const float4*)(pA + k0 + 8)  : z;
        float4 a3 = aok ? *(const float4*)(pA + k0 + 12) : z;
        *(uint4*)&sA[ar][ao]     = cvt8_f16(a0, a1);
        *(uint4*)&sA[ar][ao + 8] = cvt8_f16(a2, a3);
        *(uint2*)&sB[br][bo] = *(const uint2*)(pB + k0);
        __syncthreads();
#pragma unroll
        for (int kk = 0; kk < 32; kk += 16) {
            uint32_t af[2][4], bf[2][2];
            const int arow = wr + (lane >> 2);
            const int acol = kk + (lane & 3) * 2;
#pragma unroll
            for (int mt = 0; mt < 2; mt++) {
                const int r0 = arow + mt * 16;
                af[mt][0] = *(const uint32_t*)&sA[r0][acol];
                af[mt][1] = *(const uint32_t*)&sA[r0 + 8][acol];
                af[mt][2] = *(const uint32_t*)&sA[r0][acol + 8];
                af[mt][3] = *(const uint32_t*)&sA[r0 + 8][acol + 8];
            }
#pragma unroll
            for (int nt = 0; nt < 2; nt++) {
                const int nr = wc + nt * 8 + (lane >> 2);
                bf[nt][0] = *(const uint32_t*)&sB[nr][acol];
                bf[nt][1] = *(const uint32_t*)&sB[nr][acol + 8];
            }
#pragma unroll
            for (int mt = 0; mt < 2; mt++)
#pragma unroll
                for (int nt = 0; nt < 2; nt++)
                    MMA_F16(acc[mt][nt], af[mt], bf[nt]);
        }
        __syncthreads();
    }
    const int grp = lane >> 2, qc = (lane & 3) * 2;
#pragma unroll
    for (int mt = 0; mt < 2; mt++)
#pragma unroll
        for (int nt = 0; nt < 2; nt++) {
            const int rg = m0 + wr + mt * 16 + grp;
            const int cg = h * 32 + wc + nt * 8 + qc;
            if (rg < M)
                *(float2*)&g_V[(size_t)rg * 256 + cg] =
                    make_float2(acc[mt][nt][0], acc[mt][nt][1]);
            if (rg + 8 < M)
                *(float2*)&g_V[(size_t)(rg + 8) * 256 + cg] =
                    make_float2(acc[mt][nt][2], acc[mt][nt][3]);
        }
}

// ---------------- attention: warp-per-node (unchanged core) ----------------
__global__ __launch_bounds__(128) void attn_fused(
        const float* __restrict__ ccw, const float* __restrict__ cw,
        const void* __restrict__ ccwm, const void* __restrict__ cwm,
        const int* __restrict__ pidx, int N) {
    __shared__ float p_sm[4][8][20];
    const int t = threadIdx.x, lane = t & 31, w = t >> 5;
    const int n = blockIdx.x * 4 + w;
    if (n >= N) return;
    const size_t nb = n;
    const int mode = g_maskMode;
    const int myh = (((lane >> 4) & 1) << 2) | (((lane >> 3) & 1) << 1) | ((lane >> 2) & 1);
    const float NEG = __int_as_float(0xff800000);
    const float SCALE = 0.17677669529663688f;
    const size_t ppar = (size_t)pidx[n] * 512 + 256;

    float u[8][8];
#pragma unroll
    for (int h = 0; h < 8; h++)
#pragma unroll
        for (int j = 0; j < 8; j++)
            u[h][j] = g_U[nb * 2048 + h * 256 + j * 32 + lane];

    float sc[18];
#pragma unroll
    for (int s = 0; s < 18; s++) {
        const float* src;
        if (s < 8)       src = ccw + nb * 2048 + (size_t)s * 256;
        else if (s == 8) src = g_SP + nb * 512;
        else if (s == 9) src = g_SP + ppar;
        else             src = cw + nb * 2048 + (size_t)(s - 10) * 256;
        float m[8];
#pragma unroll
        for (int j = 0; j < 8; j++) m[j] = src[j * 32 + lane];
        float part[8];
#pragma unroll
        for (int h = 0; h < 8; h++) {
            float p = 0.f;
#pragma unroll
            for (int j = 0; j < 8; j++) p += m[j] * u[h][j];
            part[h] = p;
        }
#pragma unroll
        for (int i = 0; i < 4; i++) {
            float a = part[i], b = part[i + 4];
            float send = (lane & 16) ? a : b;
            float recv = __shfl_xor_sync(0xFFFFFFFFu, send, 16);
            part[i] = ((lane & 16) ? b : a) + recv;
        }
#pragma unroll
        for (int i = 0; i < 2; i++) {
            float a = part[i], b = part[i + 2];
            float send = (lane & 8) ? a : b;
            float recv = __shfl_xor_sync(0xFFFFFFFFu, send, 8);
            part[i] = ((lane & 8) ? b : a) + recv;
        }
        {
            float a = part[0], b = part[1];
            float send = (lane & 4) ? a : b;
            float recv = __shfl_xor_sync(0xFFFFFFFFu, send, 4);
            part[0] = ((lane & 4) ? b : a) + recv;
        }
        part[0] += __shfl_xor_sync(0xFFFFFFFFu, part[0], 2);
        part[0] += __shfl_xor_sync(0xFFFFFFFFu, part[0], 1);
        sc[s] = part[0];
    }

    unsigned vb = 3u << 8;
#pragma unroll
    for (int s = 0; s < 8; s++)
        if (mask_at(ccwm, n * 8 + s, mode)) vb |= 1u << s;
#pragma unroll
    for (int s = 0; s < 8; s++)
        if (mask_at(cwm, n * 8 + s, mode)) vb |= 1u << (10 + s);
    float mx = NEG;
#pragma unroll
    for (int s = 0; s < 18; s++)
        if ((vb >> s) & 1) mx = fmaxf(mx, sc[s] * SCALE);
    float sum = 0.f;
    float pr[18];
#pragma unroll
    for (int s = 0; s < 18; s++) {
        float e = ((vb >> s) & 1) ? __expf(sc[s] * SCALE - mx) : 0.f;
        pr[s] = e;
        sum += e;
    }
    const float inv = 1.f / sum;
    if ((lane & 3) == 0) {
#pragma unroll
        for (int s = 0; s < 18; s++) p_sm[w][myh][s] = pr[s] * inv;
    }
    __syncwarp();

    float acc[8][8];
#pragma unroll
    for (int h = 0; h < 8; h++)
#pragma unroll
        for (int j = 0; j < 8; j++) acc[h][j] = 0.f;
#pragma unroll
    for (int s = 0; s < 18; s++) {
        const float* src;
        if (s < 8)       src = ccw + nb * 2048 + (size_t)s * 256;
        else if (s == 8) src = g_SP + nb * 512;
        else if (s == 9) src = g_SP + ppar;
        else             src = cw + nb * 2048 + (size_t)(s - 10) * 256;
        float m[8];
#pragma unroll
        for (int j = 0; j < 8; j++) m[j] = src[j * 32 + lane];
#pragma unroll
        for (int h = 0; h < 8; h++) {
            float ph = p_sm[w][h][s];
#pragma unroll
            for (int j = 0; j < 8; j++) acc[h][j] += ph * m[j];
        }
    }
#pragma unroll
    for (int h = 0; h < 8; h++)
#pragma unroll
        for (int j = 0; j < 8; j++)
            g_A[nb * 2048 + h * 256 + j * 32 + lane] = acc[h][j];
}

extern "C" void kernel_launch(void* const* d_in, const int* in_sizes, int n_in,
                              void* d_out, int out_size) {
    const float* X    = (const float*)d_in[0];
    const int*   pidx = (const int*)d_in[1];
    const float* ccw  = (const float*)d_in[2];
    const void*  ccwm = d_in[3];
    const float* cw   = (const float*)d_in[4];
    const void*  cwm  = d_in[5];
    const float* Wself = (const float*)d_in[6];
    const float* Wpar  = (const float*)d_in[7];
    const float* Wq    = (const float*)d_in[8];
    const float* Wk    = (const float*)d_in[9];
    const float* Wv    = (const float*)d_in[10];
    const float* Wfin  = (const float*)d_in[11];
    float* out = (float*)d_out;
    const int N = in_sizes[0] / 256;

    float *pK, *pV, *pSP;
    __nv_bfloat16 *pWkh, *pWkl;
    __half *pWspH, *pWfinH;
    cudaGetSymbolAddress((void**)&pK, g_K);
    cudaGetSymbolAddress((void**)&pV, g_V);
    cudaGetSymbolAddress((void**)&pSP, g_SP);
    cudaGetSymbolAddress((void**)&pWkh, g_Wkh);
    cudaGetSymbolAddress((void**)&pWkl, g_Wkl);
    cudaGetSymbolAddress((void**)&pWspH, g_WspH);
    cudaGetSymbolAddress((void**)&pWfinH, g_WfinH);

    detect_kernel<<<1, 256>>>((const unsigned char*)ccwm, in_sizes[3]);
    prep_weights<<<dim3(64, 6), 1024>>>(Wself, Wpar, Wfin, Wv, Wk, Wq);

    const int MB = (N + 127) / 128;
    gemm_f16<<<dim3(MB, 8), 256>>>(X, 256, pWspH, pSP, 512, N);        // S|P
    gemm_f32s<<<dim3(MB, 4), 256>>>(ccw, 2048, pWkh, pWkl, pK, N);     // K (score path)
    u_tc<<<dim3(MB, 4, 8), 256>>>(N);                                  // U (score path)
    attn_fused<<<(N + 3) / 4, 128>>>(ccw, cw, ccwm, cwm, pidx, N);
    vproj_f16<<<dim3(MB, 8), 256>>>(N);
    gemm_f16<<<dim3(MB, 4), 256>>>(pV, 256, pWfinH, out, 256, N);      // final
}

// round 8
// speedup vs baseline: 2.0871x; 1.0779x over previous
#include <cuda_runtime.h>
#include <cuda_bf16.h>
#include <cuda_fp16.h>
#include <cstdint>
#include <cstddef>

#define MAXN 30000

__device__ float g_K[(size_t)MAXN * 256];
__device__ float g_SP[(size_t)MAXN * 512];
__device__ __half g_V[(size_t)MAXN * 256];
__device__ __half g_U[(size_t)MAXN * 8 * 256];
__device__ __half g_A[(size_t)MAXN * 8 * 256];
__device__ __nv_bfloat16 g_Wkh[256 * 256], g_Wkl[256 * 256];
__device__ __nv_bfloat16 g_WqTh[256 * 256], g_WqTl[256 * 256];
__device__ __half g_WspH[512 * 256];
__device__ __half g_WfinH[256 * 256];
__device__ __half g_WvH[256 * 256];
__device__ int g_maskMode;

// ---------------- mask dtype detection (deterministic) ----------------
__global__ void detect_kernel(const unsigned char* __restrict__ m, int nelem) {
    __shared__ int s_nzoff, s_badf, s_anyf;
    if (threadIdx.x == 0) { s_nzoff = 0; s_badf = 0; s_anyf = 0; }
    __syncthreads();
    int words = min(nelem / 4, 1024);
    const unsigned int* wm = (const unsigned int*)m;
    int nz = 0, bf = 0, af = 0;
    for (int i = threadIdx.x; i < words; i += blockDim.x) {
        unsigned int w = wm[i];
        if (w >> 8) nz = 1;
        if (w != 0u && w != 0x3F800000u) bf = 1;
        if (w == 0x3F800000u) af = 1;
    }
    if (nz) atomicOr(&s_nzoff, 1);
    if (bf) atomicOr(&s_badf, 1);
    if (af) atomicOr(&s_anyf, 1);
    __syncthreads();
    if (threadIdx.x == 0)
        g_maskMode = (!s_badf && s_anyf) ? 2 : (!s_nzoff ? 1 : 0);
}

__device__ __forceinline__ bool mask_at(const void* p, int i, int mode) {
    if (mode == 0) return ((const unsigned char*)p)[i] != 0;
    if (mode == 1) return ((const int*)p)[i] != 0;
    return ((const float*)p)[i] != 0.0f;
}

// ---------------- weight prep: one kernel, 6 jobs ----------------
__global__ void prep_weights(const float* __restrict__ Wself, const float* __restrict__ Wpar,
                             const float* __restrict__ Wfin, const float* __restrict__ Wv,
                             const float* __restrict__ Wk, const float* __restrict__ Wq) {
    int r = blockIdx.x * 4 + (threadIdx.x >> 8);
    int c = threadIdx.x & 255;
    int job = blockIdx.y;
    size_t idx = (size_t)r * 256 + c;
    switch (job) {
        case 0: g_WspH[idx] = __float2half_rn(Wself[idx]); break;
        case 1: g_WspH[idx + 256 * 256] = __float2half_rn(Wpar[idx]); break;
        case 2: g_WfinH[idx] = __float2half_rn(Wfin[idx]); break;
        case 3: g_WvH[idx] = __float2half_rn(Wv[idx]); break;
        case 4: {
            float x = Wk[idx];
            __nv_bfloat16 h = __float2bfloat16(x);
            g_Wkh[idx] = h;
            g_Wkl[idx] = __float2bfloat16(x - __bfloat162float(h));
            break;
        }
        case 5: {
            float x = Wq[(size_t)c * 256 + r];  // transpose
            __nv_bfloat16 h = __float2bfloat16(x);
            g_WqTh[idx] = h;
            g_WqTl[idx] = __float2bfloat16(x - __bfloat162float(h));
            break;
        }
    }
}

// ---------------- helpers ----------------
__device__ __forceinline__ void split8(float4 a, float4 b, uint4& h, uint4& l) {
    float x[8] = {a.x, a.y, a.z, a.w, b.x, b.y, b.z, b.w};
    uint32_t hw[4], lw[4];
#pragma unroll
    for (int p = 0; p < 4; p++) {
        __nv_bfloat16 h0 = __float2bfloat16(x[2 * p]);
        __nv_bfloat16 h1 = __float2bfloat16(x[2 * p + 1]);
        __nv_bfloat16 l0 = __float2bfloat16(x[2 * p] - __bfloat162float(h0));
        __nv_bfloat16 l1 = __float2bfloat16(x[2 * p + 1] - __bfloat162float(h1));
        hw[p] = ((uint32_t)__bfloat16_as_ushort(h1) << 16) | __bfloat16_as_ushort(h0);
        lw[p] = ((uint32_t)__bfloat16_as_ushort(l1) << 16) | __bfloat16_as_ushort(l0);
    }
    h = make_uint4(hw[0], hw[1], hw[2], hw[3]);
    l = make_uint4(lw[0], lw[1], lw[2], lw[3]);
}

__device__ __forceinline__ uint4 cvt8_f16(float4 a, float4 b) {
    uint32_t w[4];
    w[0] = ((uint32_t)__half_as_ushort(__float2half_rn(a.y)) << 16) | __half_as_ushort(__float2half_rn(a.x));
    w[1] = ((uint32_t)__half_as_ushort(__float2half_rn(a.w)) << 16) | __half_as_ushort(__float2half_rn(a.z));
    w[2] = ((uint32_t)__half_as_ushort(__float2half_rn(b.y)) << 16) | __half_as_ushort(__float2half_rn(b.x));
    w[3] = ((uint32_t)__half_as_ushort(__float2half_rn(b.w)) << 16) | __half_as_ushort(__float2half_rn(b.z));
    return make_uint4(w[0], w[1], w[2], w[3]);
}

#define MMA_BF16(d, a, b) asm volatile( \
    "mma.sync.aligned.m16n8k16.row.col.f32.bf16.bf16.f32 " \
    "{%0,%1,%2,%3}, {%4,%5,%6,%7}, {%8,%9}, {%0,%1,%2,%3};\n" \
    : "+f"(d[0]), "+f"(d[1]), "+f"(d[2]), "+f"(d[3]) \
    : "r"(a[0]), "r"(a[1]), "r"(a[2]), "r"(a[3]), "r"(b[0]), "r"(b[1]))

#define MMA_F16(d, a, b) asm volatile( \
    "mma.sync.aligned.m16n8k16.row.col.f32.f16.f16.f32 " \
    "{%0,%1,%2,%3}, {%4,%5,%6,%7}, {%8,%9}, {%0,%1,%2,%3};\n" \
    : "+f"(d[0]), "+f"(d[1]), "+f"(d[2]), "+f"(d[3]) \
    : "r"(a[0]), "r"(a[1]), "r"(a[2]), "r"(a[3]), "r"(b[0]), "r"(b[1]))

// ---------------- 3-split bf16 GEMM (score path): C = A @ B^T ----------------
// Register-prefetch pipeline: next iter's LDGs issue before this iter's MMAs.
__global__ __launch_bounds__(256) void gemm_f32s(
    const float* __restrict__ A, long lda,
    const __nv_bfloat16* __restrict__ Bh, const __nv_bfloat16* __restrict__ Bl,
    float* __restrict__ C, int M) {
    __shared__ __nv_bfloat16 sAh[128][40], sAl[128][40];
    __shared__ __nv_bfloat16 sBh[64][40], sBl[64][40];
    const int t = threadIdx.x, lane = t & 31, w = t >> 5;
    const int m0 = blockIdx.x * 128, n0 = blockIdx.y * 64;
    const int wr = (w & 3) * 32, wc = (w >> 2) * 32;
    float acc[2][4][4];
#pragma unroll
    for (int i = 0; i < 2; i++)
#pragma unroll
        for (int j = 0; j < 4; j++)
#pragma unroll
            for (int q = 0; q < 4; q++) acc[i][j][q] = 0.f;

    const int ar = t >> 1, ao = (t & 1) * 16;
    const int br = t >> 2, bo = (t & 3) * 8;
    const int am = m0 + ar;
    const bool aok = (am < M);
    const float* pA = A + (size_t)(aok ? am : 0) * lda + ao;
    const __nv_bfloat16* pBh = Bh + (size_t)(n0 + br) * 256 + bo;
    const __nv_bfloat16* pBl = Bl + (size_t)(n0 + br) * 256 + bo;

    const float4 z = make_float4(0, 0, 0, 0);
    float4 a0 = aok ? *(const float4*)(pA)      : z;
    float4 a1 = aok ? *(const float4*)(pA + 4)  : z;
    float4 a2 = aok ? *(const float4*)(pA + 8)  : z;
    float4 a3 = aok ? *(const float4*)(pA + 12) : z;
    uint4 rbh = *(const uint4*)(pBh);
    uint4 rbl = *(const uint4*)(pBl);

    for (int k0 = 0; k0 < 256; k0 += 32) {
        uint4 h0, l0, h1, l1;
        split8(a0, a1, h0, l0);
        split8(a2, a3, h1, l1);
        *(uint4*)&sAh[ar][ao]     = h0;
        *(uint4*)&sAh[ar][ao + 8] = h1;
        *(uint4*)&sAl[ar][ao]     = l0;
        *(uint4*)&sAl[ar][ao + 8] = l1;
        *(uint4*)&sBh[br][bo] = rbh;
        *(uint4*)&sBl[br][bo] = rbl;
        __syncthreads();
        if (k0 + 32 < 256) {
            const int kn = k0 + 32;
            a0 = aok ? *(const float4*)(pA + kn)      : z;
            a1 = aok ? *(const float4*)(pA + kn + 4)  : z;
            a2 = aok ? *(const float4*)(pA + kn + 8)  : z;
            a3 = aok ? *(const float4*)(pA + kn + 12) : z;
            rbh = *(const uint4*)(pBh + kn);
            rbl = *(const uint4*)(pBl + kn);
        }
#pragma unroll
        for (int kk = 0; kk < 32; kk += 16) {
            uint32_t afh[2][4], afl[2][4], bfh[4][2], bfl[4][2];
            const int arow = wr + (lane >> 2);
            const int acol = kk + (lane & 3) * 2;
#pragma unroll
            for (int mt = 0; mt < 2; mt++) {
                const int r0 = arow + mt * 16;
                afh[mt][0] = *(const uint32_t*)&sAh[r0][acol];
                afh[mt][1] = *(const uint32_t*)&sAh[r0 + 8][acol];
                afh[mt][2] = *(const uint32_t*)&sAh[r0][acol + 8];
                afh[mt][3] = *(const uint32_t*)&sAh[r0 + 8][acol + 8];
                afl[mt][0] = *(const uint32_t*)&sAl[r0][acol];
                afl[mt][1] = *(const uint32_t*)&sAl[r0 + 8][acol];
                afl[mt][2] = *(const uint32_t*)&sAl[r0][acol + 8];
                afl[mt][3] = *(const uint32_t*)&sAl[r0 + 8][acol + 8];
            }
#pragma unroll
            for (int nt = 0; nt < 4; nt++) {
                const int nr = wc + nt * 8 + (lane >> 2);
                bfh[nt][0] = *(const uint32_t*)&sBh[nr][acol];
                bfh[nt][1] = *(const uint32_t*)&sBh[nr][acol + 8];
                bfl[nt][0] = *(const uint32_t*)&sBl[nr][acol];
                bfl[nt][1] = *(const uint32_t*)&sBl[nr][acol + 8];
            }
#pragma unroll
            for (int mt = 0; mt < 2; mt++)
#pragma unroll
                for (int nt = 0; nt < 4; nt++) {
                    MMA_BF16(acc[mt][nt], afh[mt], bfh[nt]);
                    MMA_BF16(acc[mt][nt], afh[mt], bfl[nt]);
                    MMA_BF16(acc[mt][nt], afl[mt], bfh[nt]);
                }
        }
        __syncthreads();
    }
    const int grp = lane >> 2, qc = (lane & 3) * 2;
#pragma unroll
    for (int mt = 0; mt < 2; mt++)
#pragma unroll
        for (int nt = 0; nt < 4; nt++) {
            const int rg = m0 + wr + mt * 16 + grp;
            const int cg = n0 + wc + nt * 8 + qc;
            if (rg < M)
                *(float2*)&C[(size_t)rg * 256 + cg] =
                    make_float2(acc[mt][nt][0], acc[mt][nt][1]);
            if (rg + 8 < M)
                *(float2*)&C[(size_t)(rg + 8) * 256 + cg] =
                    make_float2(acc[mt][nt][2], acc[mt][nt][3]);
        }
}

// ---------------- fp16 GEMM, A fp32 in gmem: C = A @ B^T (fp32 out) --------
__global__ __launch_bounds__(256) void gemm_f16(
    const float* __restrict__ A, long lda,
    const __half* __restrict__ B,
    float* __restrict__ C, long ldc, int M) {
    __shared__ __half sA[128][40];
    __shared__ __half sB[64][40];
    const int t = threadIdx.x, lane = t & 31, w = t >> 5;
    const int m0 = blockIdx.x * 128, n0 = blockIdx.y * 64;
    const int wr = (w & 3) * 32, wc = (w >> 2) * 32;
    float acc[2][4][4];
#pragma unroll
    for (int i = 0; i < 2; i++)
#pragma unroll
        for (int j = 0; j < 4; j++)
#pragma unroll
            for (int q = 0; q < 4; q++) acc[i][j][q] = 0.f;

    const int ar = t >> 1, ao = (t & 1) * 16;
    const int br = t >> 2, bo = (t & 3) * 8;
    const int am = m0 + ar;
    const bool aok = (am < M);
    const float* pA = A + (size_t)(aok ? am : 0) * lda + ao;
    const __half* pB = B + (size_t)(n0 + br) * 256 + bo;

    const float4 z = make_float4(0, 0, 0, 0);
    float4 a0 = aok ? *(const float4*)(pA)      : z;
    float4 a1 = aok ? *(const float4*)(pA + 4)  : z;
    float4 a2 = aok ? *(const float4*)(pA + 8)  : z;
    float4 a3 = aok ? *(const float4*)(pA + 12) : z;
    uint4 rb = *(const uint4*)(pB);

    for (int k0 = 0; k0 < 256; k0 += 32) {
        *(uint4*)&sA[ar][ao]     = cvt8_f16(a0, a1);
        *(uint4*)&sA[ar][ao + 8] = cvt8_f16(a2, a3);
        *(uint4*)&sB[br][bo] = rb;
        __syncthreads();
        if (k0 + 32 < 256) {
            const int kn = k0 + 32;
            a0 = aok ? *(const float4*)(pA + kn)      : z;
            a1 = aok ? *(const float4*)(pA + kn + 4)  : z;
            a2 = aok ? *(const float4*)(pA + kn + 8)  : z;
            a3 = aok ? *(const float4*)(pA + kn + 12) : z;
            rb = *(const uint4*)(pB + kn);
        }
#pragma unroll
        for (int kk = 0; kk < 32; kk += 16) {
            uint32_t af[2][4], bf[4][2];
            const int arow = wr + (lane >> 2);
            const int acol = kk + (lane & 3) * 2;
#pragma unroll
            for (int mt = 0; mt < 2; mt++) {
                const int r0 = arow + mt * 16;
                af[mt][0] = *(const uint32_t*)&sA[r0][acol];
                af[mt][1] = *(const uint32_t*)&sA[r0 + 8][acol];
                af[mt][2] = *(const uint32_t*)&sA[r0][acol + 8];
                af[mt][3] = *(const uint32_t*)&sA[r0 + 8][acol + 8];
            }
#pragma unroll
            for (int nt = 0; nt < 4; nt++) {
                const int nr = wc + nt * 8 + (lane >> 2);
                bf[nt][0] = *(const uint32_t*)&sB[nr][acol];
                bf[nt][1] = *(const uint32_t*)&sB[nr][acol + 8];
            }
#pragma unroll
            for (int mt = 0; mt < 2; mt++)
#pragma unroll
                for (int nt = 0; nt < 4; nt++)
                    MMA_F16(acc[mt][nt], af[mt], bf[nt]);
        }
        __syncthreads();
    }
    const int grp = lane >> 2, qc = (lane & 3) * 2;
#pragma unroll
    for (int mt = 0; mt < 2; mt++)
#pragma unroll
        for (int nt = 0; nt < 4; nt++) {
            const int rg = m0 + wr + mt * 16 + grp;
            const int cg = n0 + wc + nt * 8 + qc;
            if (rg < M)
                *(float2*)&C[(size_t)rg * ldc + cg] =
                    make_float2(acc[mt][nt][0], acc[mt][nt][1]);
            if (rg + 8 < M)
                *(float2*)&C[(size_t)(rg + 8) * ldc + cg] =
                    make_float2(acc[mt][nt][2], acc[mt][nt][3]);
        }
}

// ---------------- fp16 GEMM, A fp16 in gmem (final proj): C fp32 -----------
__global__ __launch_bounds__(256) void gemm_h16(
    const __half* __restrict__ A,
    const __half* __restrict__ B,
    float* __restrict__ C, int M) {
    __shared__ __half sA[128][40];
    __shared__ __half sB[64][40];
    const int t = threadIdx.x, lane = t & 31, w = t >> 5;
    const int m0 = blockIdx.x * 128, n0 = blockIdx.y * 64;
    const int wr = (w & 3) * 32, wc = (w >> 2) * 32;
    float acc[2][4][4];
#pragma unroll
    for (int i = 0; i < 2; i++)
#pragma unroll
        for (int j = 0; j < 4; j++)
#pragma unroll
            for (int q = 0; q < 4; q++) acc[i][j][q] = 0.f;

    const int ar = t >> 1, ao = (t & 1) * 16;
    const int br = t >> 2, bo = (t & 3) * 8;
    const int am = m0 + ar;
    const bool aok = (am < M);
    const __half* pA = A + (size_t)(aok ? am : 0) * 256 + ao;
    const __half* pB = B + (size_t)(n0 + br) * 256 + bo;

    const uint4 uz = make_uint4(0, 0, 0, 0);
    uint4 ra0 = aok ? *(const uint4*)(pA)     : uz;
    uint4 ra1 = aok ? *(const uint4*)(pA + 8) : uz;
    uint4 rb  = *(const uint4*)(pB);

    for (int k0 = 0; k0 < 256; k0 += 32) {
        *(uint4*)&sA[ar][ao]     = ra0;
        *(uint4*)&sA[ar][ao + 8] = ra1;
        *(uint4*)&sB[br][bo] = rb;
        __syncthreads();
        if (k0 + 32 < 256) {
            const int kn = k0 + 32;
            ra0 = aok ? *(const uint4*)(pA + kn)     : uz;
            ra1 = aok ? *(const uint4*)(pA + kn + 8) : uz;
            rb  = *(const uint4*)(pB + kn);
        }
#pragma unroll
        for (int kk = 0; kk < 32; kk += 16) {
            uint32_t af[2][4], bf[4][2];
            const int arow = wr + (lane >> 2);
            const int acol = kk + (lane & 3) * 2;
#pragma unroll
            for (int mt = 0; mt < 2; mt++) {
                const int r0 = arow + mt * 16;
                af[mt][0] = *(const uint32_t*)&sA[r0][acol];
                af[mt][1] = *(const uint32_t*)&sA[r0 + 8][acol];
                af[mt][2] = *(const uint32_t*)&sA[r0][acol + 8];
                af[mt][3] = *(const uint32_t*)&sA[r0 + 8][acol + 8];
            }
#pragma unroll
            for (int nt = 0; nt < 4; nt++) {
                const int nr = wc + nt * 8 + (lane >> 2);
                bf[nt][0] = *(const uint32_t*)&sB[nr][acol];
                bf[nt][1] = *(const uint32_t*)&sB[nr][acol + 8];
            }
#pragma unroll
            for (int mt = 0; mt < 2; mt++)
#pragma unroll
                for (int nt = 0; nt < 4; nt++)
                    MMA_F16(acc[mt][nt], af[mt], bf[nt]);
        }
        __syncthreads();
    }
    const int grp = lane >> 2, qc = (lane & 3) * 2;
#pragma unroll
    for (int mt = 0; mt < 2; mt++)
#pragma unroll
        for (int nt = 0; nt < 4; nt++) {
            const int rg = m0 + wr + mt * 16 + grp;
            const int cg = n0 + wc + nt * 8 + qc;
            if (rg < M)
                *(float2*)&C[(size_t)rg * 256 + cg] =
                    make_float2(acc[mt][nt][0], acc[mt][nt][1]);
            if (rg + 8 < M)
                *(float2*)&C[(size_t)(rg + 8) * 256 + cg] =
                    make_float2(acc[mt][nt][2], acc[mt][nt][3]);
        }
}

// ---------------- u via tensor cores (3-split bf16), fp16 output ------------
__global__ __launch_bounds__(256) void u_tc(int M) {
    __shared__ __nv_bfloat16 sAh[128][40], sAl[128][40];
    __shared__ __nv_bfloat16 sBh[64][40], sBl[64][40];
    const int t = threadIdx.x, lane = t & 31, w = t >> 5;
    const int m0 = blockIdx.x * 128, i0 = blockIdx.y * 64, h = blockIdx.z;
    const int wr = (w & 3) * 32, wc = (w >> 2) * 32;
    float acc[2][4][4];
#pragma unroll
    for (int i = 0; i < 2; i++)
#pragma unroll
        for (int j = 0; j < 4; j++)
#pragma unroll
            for (int q = 0; q < 4; q++) acc[i][j][q] = 0.f;

    const int ar = t >> 1, ao = (t & 1) * 16;
    const int br = t >> 2, bo = (t & 3) * 8;
    const int am = m0 + ar;
    const bool aok = (am < M);
    {
        float4 z = make_float4(0, 0, 0, 0);
        const float* pA = g_K + (size_t)(aok ? am : 0) * 256 + h * 32 + ao;
        float4 a0 = aok ? *(const float4*)(pA)      : z;
        float4 a1 = aok ? *(const float4*)(pA + 4)  : z;
        float4 a2 = aok ? *(const float4*)(pA + 8)  : z;
        float4 a3 = aok ? *(const float4*)(pA + 12) : z;
        uint4 h0, l0, h1, l1;
        split8(a0, a1, h0, l0);
        split8(a2, a3, h1, l1);
        *(uint4*)&sAh[ar][ao]     = h0;
        *(uint4*)&sAh[ar][ao + 8] = h1;
        *(uint4*)&sAl[ar][ao]     = l0;
        *(uint4*)&sAl[ar][ao + 8] = l1;
        *(uint4*)&sBh[br][bo] = *(const uint4*)&g_WqTh[(size_t)(i0 + br) * 256 + h * 32 + bo];
        *(uint4*)&sBl[br][bo] = *(const uint4*)&g_WqTl[(size_t)(i0 + br) * 256 + h * 32 + bo];
    }
    __syncthreads();
#pragma unroll
    for (int kk = 0; kk < 32; kk += 16) {
        uint32_t afh[2][4], afl[2][4], bfh[4][2], bfl[4][2];
        const int arow = wr + (lane >> 2);
        const int acol = kk + (lane & 3) * 2;
#pragma unroll
        for (int mt = 0; mt < 2; mt++) {
            const int r0 = arow + mt * 16;
            afh[mt][0] = *(const uint32_t*)&sAh[r0][acol];
            afh[mt][1] = *(const uint32_t*)&sAh[r0 + 8][acol];
            afh[mt][2] = *(const uint32_t*)&sAh[r0][acol + 8];
            afh[mt][3] = *(const uint32_t*)&sAh[r0 + 8][acol + 8];
            afl[mt][0] = *(const uint32_t*)&sAl[r0][acol];
            afl[mt][1] = *(const uint32_t*)&sAl[r0 + 8][acol];
            afl[mt][2] = *(const uint32_t*)&sAl[r0][acol + 8];
            afl[mt][3] = *(const uint32_t*)&sAl[r0 + 8][acol + 8];
        }
#pragma unroll
        for (int nt = 0; nt < 4; nt++) {
            const int nr = wc + nt * 8 + (lane >> 2);
            bfh[nt][0] = *(const uint32_t*)&sBh[nr][acol];
            bfh[nt][1] = *(const uint32_t*)&sBh[nr][acol + 8];
            bfl[nt][0] = *(const uint32_t*)&sBl[nr][acol];
            bfl[nt][1] = *(const uint32_t*)&sBl[nr][acol + 8];
        }
#pragma unroll
        for (int mt = 0; mt < 2; mt++)
#pragma unroll
            for (int nt = 0; nt < 4; nt++) {
                MMA_BF16(acc[mt][nt], afh[mt], bfh[nt]);
                MMA_BF16(acc[mt][nt], afh[mt], bfl[nt]);
                MMA_BF16(acc[mt][nt], afl[mt], bfh[nt]);
            }
    }
    const int grp = lane >> 2, qc = (lane & 3) * 2;
#pragma unroll
    for (int mt = 0; mt < 2; mt++)
#pragma unroll
        for (int nt = 0; nt < 4; nt++) {
            const int rg = m0 + wr + mt * 16 + grp;
            const int cg = h * 256 + i0 + wc + nt * 8 + qc;
            if (rg < M) {
                __half2 v = __floats2half2_rn(acc[mt][nt][0], acc[mt][nt][1]);
                *(__half2*)&g_U[(size_t)rg * 2048 + cg] = v;
            }
            if (rg + 8 < M) {
                __half2 v = __floats2half2_rn(acc[mt][nt][2], acc[mt][nt][3]);
                *(__half2*)&g_U[(size_t)(rg + 8) * 2048 + cg] = v;
            }
        }
}

// ---------------- vproj: A fp16 in gmem, fp16 Wv, fp16 V out ---------------
__global__ __launch_bounds__(256) void vproj_f16(int M) {
    __shared__ __half sA[128][40];
    __shared__ __half sB[32][40];
    const int t = threadIdx.x, lane = t & 31, w = t >> 5;
    const int m0 = blockIdx.x * 128, h = blockIdx.y;
    const int wr = (w & 3) * 32, wc = (w >> 2) * 16;
    float acc[2][2][4];
#pragma unroll
    for (int i = 0; i < 2; i++)
#pragma unroll
        for (int j = 0; j < 2; j++)
#pragma unroll
            for (int q = 0; q < 4; q++) acc[i][j][q] = 0.f;

    const int ar = t >> 1, ao = (t & 1) * 16;
    const int br = t >> 3, bo = (t & 7) * 4;
    const int am = m0 + ar;
    const bool aok = (am < M);
    const __half* pA = g_A + (size_t)(aok ? am : 0) * 2048 + h * 256 + ao;
    const __half* pB = g_WvH + (size_t)(h * 32 + br) * 256 + bo;

    const uint4 uz = make_uint4(0, 0, 0, 0);
    uint4 ra0 = aok ? *(const uint4*)(pA)     : uz;
    uint4 ra1 = aok ? *(const uint4*)(pA + 8) : uz;
    uint2 rb  = *(const uint2*)(pB);

    for (int k0 = 0; k0 < 256; k0 += 32) {
        *(uint4*)&sA[ar][ao]     = ra0;
        *(uint4*)&sA[ar][ao + 8] = ra1;
        *(uint2*)&sB[br][bo] = rb;
        __syncthreads();
        if (k0 + 32 < 256) {
            const int kn = k0 + 32;
            ra0 = aok ? *(const uint4*)(pA + kn)     : uz;
            ra1 = aok ? *(const uint4*)(pA + kn + 8) : uz;
            rb  = *(const uint2*)(pB + kn);
        }
#pragma unroll
        for (int kk = 0; kk < 32; kk += 16) {
            uint32_t af[2][4], bf[2][2];
            const int arow = wr + (lane >> 2);
            const int acol = kk + (lane & 3) * 2;
#pragma unroll
            for (int mt = 0; mt < 2; mt++) {
                const int r0 = arow + mt * 16;
                af[mt][0] = *(const uint32_t*)&sA[r0][acol];
                af[mt][1] = *(const uint32_t*)&sA[r0 + 8][acol];
                af[mt][2] = *(const uint32_t*)&sA[r0][acol + 8];
                af[mt][3] = *(const uint32_t*)&sA[r0 + 8][acol + 8];
            }
#pragma unroll
            for (int nt = 0; nt < 2; nt++) {
                const int nr = wc + nt * 8 + (lane >> 2);
                bf[nt][0] = *(const uint32_t*)&sB[nr][acol];
                bf[nt][1] = *(const uint32_t*)&sB[nr][acol + 8];
            }
#pragma unroll
            for (int mt = 0; mt < 2; mt++)
#pragma unroll
                for (int nt = 0; nt < 2; nt++)
                    MMA_F16(acc[mt][nt], af[mt], bf[nt]);
        }
        __syncthreads();
    }
    const int grp = lane >> 2, qc = (lane & 3) * 2;
#pragma unroll
    for (int mt = 0; mt < 2; mt++)
#pragma unroll
        for (int nt = 0; nt < 2; nt++) {
            const int rg = m0 + wr + mt * 16 + grp;
            const int cg = h * 32 + wc + nt * 8 + qc;
            if (rg < M) {
                __half2 v = __floats2half2_rn(acc[mt][nt][0], acc[mt][nt][1]);
                *(__half2*)&g_V[(size_t)rg * 256 + cg] = v;
            }
            if (rg + 8 < M) {
                __half2 v = __floats2half2_rn(acc[mt][nt][2], acc[mt][nt][3]);
                *(__half2*)&g_V[(size_t)(rg + 8) * 256 + cg] = v;
            }
        }
}

// ---------------- attention: warp-per-node (fp16 U in, fp16 A out) ----------
__global__ __launch_bounds__(128) void attn_fused(
        const float* __restrict__ ccw, const float* __restrict__ cw,
        const void* __restrict__ ccwm, const void* __restrict__ cwm,
        const int* __restrict__ pidx, int N) {
    __shared__ float p_sm[4][8][20];
    const int t = threadIdx.x, lane = t & 31, w = t >> 5;
    const int n = blockIdx.x * 4 + w;
    if (n >= N) return;
    const size_t nb = n;
    const int mode = g_maskMode;
    const int myh = (((lane >> 4) & 1) << 2) | (((lane >> 3) & 1) << 1) | ((lane >> 2) & 1);
    const float NEG = __int_as_float(0xff800000);
    const float SCALE = 0.17677669529663688f;
    const size_t ppar = (size_t)pidx[n] * 512 + 256;

    float u[8][8];
#pragma unroll
    for (int h = 0; h < 8; h++)
#pragma unroll
        for (int j = 0; j < 8; j++)
            u[h][j] = __half2float(g_U[nb * 2048 + h * 256 + j * 32 + lane]);

    float sc[18];
#pragma unroll
    for (int s = 0; s < 18; s++) {
        const float* src;
        if (s < 8)       src = ccw + nb * 2048 + (size_t)s * 256;
        else if (s == 8) src = g_SP + nb * 512;
        else if (s == 9) src = g_SP + ppar;
        else             src = cw + nb * 2048 + (size_t)(s - 10) * 256;
        float m[8];
#pragma unroll
        for (int j = 0; j < 8; j++) m[j] = src[j * 32 + lane];
        float part[8];
#pragma unroll
        for (int h = 0; h < 8; h++) {
            float p = 0.f;
#pragma unroll
            for (int j = 0; j < 8; j++) p += m[j] * u[h][j];
            part[h] = p;
        }
#pragma unroll
        for (int i = 0; i < 4; i++) {
            float a = part[i], b = part[i + 4];
            float send = (lane & 16) ? a : b;
            float recv = __shfl_xor_sync(0xFFFFFFFFu, send, 16);
            part[i] = ((lane & 16) ? b : a) + recv;
        }
#pragma unroll
        for (int i = 0; i < 2; i++) {
            float a = part[i], b = part[i + 2];
            float send = (lane & 8) ? a : b;
            float recv = __shfl_xor_sync(0xFFFFFFFFu, send, 8);
            part[i] = ((lane & 8) ? b : a) + recv;
        }
        {
            float a = part[0], b = part[1];
            float send = (lane & 4) ? a : b;
            float recv = __shfl_xor_sync(0xFFFFFFFFu, send, 4);
            part[0] = ((lane & 4) ? b : a) + recv;
        }
        part[0] += __shfl_xor_sync(0xFFFFFFFFu, part[0], 2);
        part[0] += __shfl_xor_sync(0xFFFFFFFFu, part[0], 1);
        sc[s] = part[0];
    }

    unsigned vb = 3u << 8;
#pragma unroll
    for (int s = 0; s < 8; s++)
        if (mask_at(ccwm, n * 8 + s, mode)) vb |= 1u << s;
#pragma unroll
    for (int s = 0; s < 8; s++)
        if (mask_at(cwm, n * 8 + s, mode)) vb |= 1u << (10 + s);
    float mx = NEG;
#pragma unroll
    for (int s = 0; s < 18; s++)
        if ((vb >> s) & 1) mx = fmaxf(mx, sc[s] * SCALE);
    float sum = 0.f;
    float pr[18];
#pragma unroll
    for (int s = 0; s < 18; s++) {
        float e = ((vb >> s) & 1) ? __expf(sc[s] * SCALE - mx) : 0.f;
        pr[s] = e;
        sum += e;
    }
    const float inv = 1.f / sum;
    if ((lane & 3) == 0) {
#pragma unroll
        for (int s = 0; s < 18; s++) p_sm[w][myh][s] = pr[s] * inv;
    }
    __syncwarp();

    float acc[8][8];
#pragma unroll
    for (int h = 0; h < 8; h++)
#pragma unroll
        for (int j = 0; j < 8; j++) acc[h][j] = 0.f;
#pragma unroll
    for (int s = 0; s < 18; s++) {
        const float* src;
        if (s < 8)       src = ccw + nb * 2048 + (size_t)s * 256;
        else if (s == 8) src = g_SP + nb * 512;
        else if (s == 9) src = g_SP + ppar;
        else             src = cw + nb * 2048 + (size_t)(s - 10) * 256;
        float m[8];
#pragma unroll
        for (int j = 0; j < 8; j++) m[j] = src[j * 32 + lane];
#pragma unroll
        for (int h = 0; h < 8; h++) {
            float ph = p_sm[w][h][s];
#pragma unroll
            for (int j = 0; j < 8; j++) acc[h][j] += ph * m[j];
        }
    }
#pragma unroll
    for (int h = 0; h < 8; h++)
#pragma unroll
        for (int j = 0; j < 8; j++)
            g_A[nb * 2048 + h * 256 + j * 32 + lane] = __float2half_rn(acc[h][j]);
}

extern "C" void kernel_launch(void* const* d_in, const int* in_sizes, int n_in,
                              void* d_out, int out_size) {
    const float* X    = (const float*)d_in[0];
    const int*   pidx = (const int*)d_in[1];
    const float* ccw  = (const float*)d_in[2];
    const void*  ccwm = d_in[3];
    const float* cw   = (const float*)d_in[4];
    const void*  cwm  = d_in[5];
    const float* Wself = (const float*)d_in[6];
    const float* Wpar  = (const float*)d_in[7];
    const float* Wq    = (const float*)d_in[8];
    const float* Wk    = (const float*)d_in[9];
    const float* Wv    = (const float*)d_in[10];
    const float* Wfin  = (const float*)d_in[11];
    float* out = (float*)d_out;
    const int N = in_sizes[0] / 256;

    float *pK, *pSP;
    __half *pV;
    __nv_bfloat16 *pWkh, *pWkl;
    __half *pWspH, *pWfinH;
    cudaGetSymbolAddress((void**)&pK, g_K);
    cudaGetSymbolAddress((void**)&pV, g_V);
    cudaGetSymbolAddress((void**)&pSP, g_SP);
    cudaGetSymbolAddress((void**)&pWkh, g_Wkh);
    cudaGetSymbolAddress((void**)&pWkl, g_Wkl);
    cudaGetSymbolAddress((void**)&pWspH, g_WspH);
    cudaGetSymbolAddress((void**)&pWfinH, g_WfinH);

    detect_kernel<<<1, 256>>>((const unsigned char*)ccwm, in_sizes[3]);
    prep_weights<<<dim3(64, 6), 1024>>>(Wself, Wpar, Wfin, Wv, Wk, Wq);

    const int MB = (N + 127) / 128;
    gemm_f16<<<dim3(MB, 8), 256>>>(X, 256, pWspH, pSP, 512, N);        // S|P
    gemm_f32s<<<dim3(MB, 4), 256>>>(ccw, 2048, pWkh, pWkl, pK, N);     // K (score path)
    u_tc<<<dim3(MB, 4, 8), 256>>>(N);                                  // U (score path)
    attn_fused<<<(N + 3) / 4, 128>>>(ccw, cw, ccwm, cwm, pidx, N);
    vproj_f16<<<dim3(MB, 8), 256>>>(N);
    gemm_h16<<<dim3(MB, 4), 256>>>(pV, pWfinH, out, N);                // final
}

// round 9
// speedup vs baseline: 2.2700x; 1.0876x over previous
#include <cuda_runtime.h>
#include <cuda_bf16.h>
#include <cuda_fp16.h>
#include <cstdint>
#include <cstddef>

#define MAXN 30000
typedef unsigned long long u64;

__device__ float g_K[(size_t)MAXN * 256];
__device__ float g_SP[(size_t)MAXN * 512];
__device__ __half g_V[(size_t)MAXN * 256];
__device__ __half g_U[(size_t)MAXN * 8 * 256];
__device__ __half g_A[(size_t)MAXN * 8 * 256];
__device__ __nv_bfloat16 g_Wkh[256 * 256], g_Wkl[256 * 256];
__device__ __nv_bfloat16 g_WqTh[256 * 256], g_WqTl[256 * 256];
__device__ __half g_WspH[512 * 256];
__device__ __half g_WfinH[256 * 256];
__device__ __half g_WvH[256 * 256];
__device__ int g_maskMode;

// packed fp32x2 ops (Blackwell; full fp32 precision, 2x issue rate)
#define PACK2(o, lo, hi) asm("mov.b64 %0, {%1,%2};" : "=l"(o) : "f"(lo), "f"(hi))
#define UNPACK2(lo, hi, v) asm("mov.b64 {%0,%1}, %2;" : "=f"(lo), "=f"(hi) : "l"(v))
#define FMA2(d, a, b, c) asm("fma.rn.f32x2 %0, %1, %2, %3;" : "=l"(d) : "l"(a), "l"(b), "l"(c))
#define MUL2(d, a, b) asm("mul.rn.f32x2 %0, %1, %2;" : "=l"(d) : "l"(a), "l"(b))

// ---------------- mask dtype detection (deterministic) ----------------
__global__ void detect_kernel(const unsigned char* __restrict__ m, int nelem) {
    __shared__ int s_nzoff, s_badf, s_anyf;
    if (threadIdx.x == 0) { s_nzoff = 0; s_badf = 0; s_anyf = 0; }
    __syncthreads();
    int words = min(nelem / 4, 1024);
    const unsigned int* wm = (const unsigned int*)m;
    int nz = 0, bf = 0, af = 0;
    for (int i = threadIdx.x; i < words; i += blockDim.x) {
        unsigned int w = wm[i];
        if (w >> 8) nz = 1;
        if (w != 0u && w != 0x3F800000u) bf = 1;
        if (w == 0x3F800000u) af = 1;
    }
    if (nz) atomicOr(&s_nzoff, 1);
    if (bf) atomicOr(&s_badf, 1);
    if (af) atomicOr(&s_anyf, 1);
    __syncthreads();
    if (threadIdx.x == 0)
        g_maskMode = (!s_badf && s_anyf) ? 2 : (!s_nzoff ? 1 : 0);
}

__device__ __forceinline__ bool mask_at(const void* p, int i, int mode) {
    if (mode == 0) return ((const unsigned char*)p)[i] != 0;
    if (mode == 1) return ((const int*)p)[i] != 0;
    return ((const float*)p)[i] != 0.0f;
}

// ---------------- weight prep: one kernel, 6 jobs ----------------
__global__ void prep_weights(const float* __restrict__ Wself, const float* __restrict__ Wpar,
                             const float* __restrict__ Wfin, const float* __restrict__ Wv,
                             const float* __restrict__ Wk, const float* __restrict__ Wq) {
    int r = blockIdx.x * 4 + (threadIdx.x >> 8);
    int c = threadIdx.x & 255;
    int job = blockIdx.y;
    size_t idx = (size_t)r * 256 + c;
    switch (job) {
        case 0: g_WspH[idx] = __float2half_rn(Wself[idx]); break;
        case 1: g_WspH[idx + 256 * 256] = __float2half_rn(Wpar[idx]); break;
        case 2: g_WfinH[idx] = __float2half_rn(Wfin[idx]); break;
        case 3: g_WvH[idx] = __float2half_rn(Wv[idx]); break;
        case 4: {
            float x = Wk[idx];
            __nv_bfloat16 h = __float2bfloat16(x);
            g_Wkh[idx] = h;
            g_Wkl[idx] = __float2bfloat16(x - __bfloat162float(h));
            break;
        }
        case 5: {
            float x = Wq[(size_t)c * 256 + r];  // transpose
            __nv_bfloat16 h = __float2bfloat16(x);
            g_WqTh[idx] = h;
            g_WqTl[idx] = __float2bfloat16(x - __bfloat162float(h));
            break;
        }
    }
}

// ---------------- helpers ----------------
__device__ __forceinline__ void split8(float4 a, float4 b, uint4& h, uint4& l) {
    float x[8] = {a.x, a.y, a.z, a.w, b.x, b.y, b.z, b.w};
    uint32_t hw[4], lw[4];
#pragma unroll
    for (int p = 0; p < 4; p++) {
        __nv_bfloat16 h0 = __float2bfloat16(x[2 * p]);
        __nv_bfloat16 h1 = __float2bfloat16(x[2 * p + 1]);
        __nv_bfloat16 l0 = __float2bfloat16(x[2 * p] - __bfloat162float(h0));
        __nv_bfloat16 l1 = __float2bfloat16(x[2 * p + 1] - __bfloat162float(h1));
        hw[p] = ((uint32_t)__bfloat16_as_ushort(h1) << 16) | __bfloat16_as_ushort(h0);
        lw[p] = ((uint32_t)__bfloat16_as_ushort(l1) << 16) | __bfloat16_as_ushort(l0);
    }
    h = make_uint4(hw[0], hw[1], hw[2], hw[3]);
    l = make_uint4(lw[0], lw[1], lw[2], lw[3]);
}

__device__ __forceinline__ uint4 cvt8_f16(float4 a, float4 b) {
    uint32_t w[4];
    w[0] = ((uint32_t)__half_as_ushort(__float2half_rn(a.y)) << 16) | __half_as_ushort(__float2half_rn(a.x));
    w[1] = ((uint32_t)__half_as_ushort(__float2half_rn(a.w)) << 16) | __half_as_ushort(__float2half_rn(a.z));
    w[2] = ((uint32_t)__half_as_ushort(__float2half_rn(b.y)) << 16) | __half_as_ushort(__float2half_rn(b.x));
    w[3] = ((uint32_t)__half_as_ushort(__float2half_rn(b.w)) << 16) | __half_as_ushort(__float2half_rn(b.z));
    return make_uint4(w[0], w[1], w[2], w[3]);
}

#define MMA_BF16(d, a, b) asm volatile( \
    "mma.sync.aligned.m16n8k16.row.col.f32.bf16.bf16.f32 " \
    "{%0,%1,%2,%3}, {%4,%5,%6,%7}, {%8,%9}, {%0,%1,%2,%3};\n" \
    : "+f"(d[0]), "+f"(d[1]), "+f"(d[2]), "+f"(d[3]) \
    : "r"(a[0]), "r"(a[1]), "r"(a[2]), "r"(a[3]), "r"(b[0]), "r"(b[1]))

#define MMA_F16(d, a, b) asm volatile( \
    "mma.sync.aligned.m16n8k16.row.col.f32.f16.f16.f32 " \
    "{%0,%1,%2,%3}, {%4,%5,%6,%7}, {%8,%9}, {%0,%1,%2,%3};\n" \
    : "+f"(d[0]), "+f"(d[1]), "+f"(d[2]), "+f"(d[3]) \
    : "r"(a[0]), "r"(a[1]), "r"(a[2]), "r"(a[3]), "r"(b[0]), "r"(b[1]))

// ---------------- 3-split bf16 GEMM (score path, no prefetch) ----------------
__global__ __launch_bounds__(256) void gemm_f32s(
    const float* __restrict__ A, long lda,
    const __nv_bfloat16* __restrict__ Bh, const __nv_bfloat16* __restrict__ Bl,
    float* __restrict__ C, int M) {
    __shared__ __nv_bfloat16 sAh[128][40], sAl[128][40];
    __shared__ __nv_bfloat16 sBh[64][40], sBl[64][40];
    const int t = threadIdx.x, lane = t & 31, w = t >> 5;
    const int m0 = blockIdx.x * 128, n0 = blockIdx.y * 64;
    const int wr = (w & 3) * 32, wc = (w >> 2) * 32;
    float acc[2][4][4];
#pragma unroll
    for (int i = 0; i < 2; i++)
#pragma unroll
        for (int j = 0; j < 4; j++)
#pragma unroll
            for (int q = 0; q < 4; q++) acc[i][j][q] = 0.f;

    const int ar = t >> 1, ao = (t & 1) * 16;
    const int br = t >> 2, bo = (t & 3) * 8;
    const int am = m0 + ar;
    const bool aok = (am < M);
    const float* pA = A + (size_t)(aok ? am : 0) * lda + ao;
    const __nv_bfloat16* pBh = Bh + (size_t)(n0 + br) * 256 + bo;
    const __nv_bfloat16* pBl = Bl + (size_t)(n0 + br) * 256 + bo;

    for (int k0 = 0; k0 < 256; k0 += 32) {
        float4 z = make_float4(0, 0, 0, 0);
        float4 a0 = aok ? *(const float4*)(pA + k0)      : z;
        float4 a1 = aok ? *(const float4*)(pA + k0 + 4)  : z;
        float4 a2 = aok ? *(const float4*)(pA + k0 + 8)  : z;
        float4 a3 = aok ? *(const float4*)(pA + k0 + 12) : z;
        uint4 h0, l0, h1, l1;
        split8(a0, a1, h0, l0);
        split8(a2, a3, h1, l1);
        *(uint4*)&sAh[ar][ao]     = h0;
        *(uint4*)&sAh[ar][ao + 8] = h1;
        *(uint4*)&sAl[ar][ao]     = l0;
        *(uint4*)&sAl[ar][ao + 8] = l1;
        *(uint4*)&sBh[br][bo] = *(const uint4*)(pBh + k0);
        *(uint4*)&sBl[br][bo] = *(const uint4*)(pBl + k0);
        __syncthreads();
#pragma unroll
        for (int kk = 0; kk < 32; kk += 16) {
            uint32_t afh[2][4], afl[2][4], bfh[4][2], bfl[4][2];
            const int arow = wr + (lane >> 2);
            const int acol = kk + (lane & 3) * 2;
#pragma unroll
            for (int mt = 0; mt < 2; mt++) {
                const int r0 = arow + mt * 16;
                afh[mt][0] = *(const uint32_t*)&sAh[r0][acol];
                afh[mt][1] = *(const uint32_t*)&sAh[r0 + 8][acol];
                afh[mt][2] = *(const uint32_t*)&sAh[r0][acol + 8];
                afh[mt][3] = *(const uint32_t*)&sAh[r0 + 8][acol + 8];
                afl[mt][0] = *(const uint32_t*)&sAl[r0][acol];
                afl[mt][1] = *(const uint32_t*)&sAl[r0 + 8][acol];
                afl[mt][2] = *(const uint32_t*)&sAl[r0][acol + 8];
                afl[mt][3] = *(const uint32_t*)&sAl[r0 + 8][acol + 8];
            }
#pragma unroll
            for (int nt = 0; nt < 4; nt++) {
                const int nr = wc + nt * 8 + (lane >> 2);
                bfh[nt][0] = *(const uint32_t*)&sBh[nr][acol];
                bfh[nt][1] = *(const uint32_t*)&sBh[nr][acol + 8];
                bfl[nt][0] = *(const uint32_t*)&sBl[nr][acol];
                bfl[nt][1] = *(const uint32_t*)&sBl[nr][acol + 8];
            }
#pragma unroll
            for (int mt = 0; mt < 2; mt++)
#pragma unroll
                for (int nt = 0; nt < 4; nt++) {
                    MMA_BF16(acc[mt][nt], afh[mt], bfh[nt]);
                    MMA_BF16(acc[mt][nt], afh[mt], bfl[nt]);
                    MMA_BF16(acc[mt][nt], afl[mt], bfh[nt]);
                }
        }
        __syncthreads();
    }
    const int grp = lane >> 2, qc = (lane & 3) * 2;
#pragma unroll
    for (int mt = 0; mt < 2; mt++)
#pragma unroll
        for (int nt = 0; nt < 4; nt++) {
            const int rg = m0 + wr + mt * 16 + grp;
            const int cg = n0 + wc + nt * 8 + qc;
            if (rg < M)
                *(float2*)&C[(size_t)rg * 256 + cg] =
                    make_float2(acc[mt][nt][0], acc[mt][nt][1]);
            if (rg + 8 < M)
                *(float2*)&C[(size_t)(rg + 8) * 256 + cg] =
                    make_float2(acc[mt][nt][2], acc[mt][nt][3]);
        }
}

// ---------------- fp16 GEMM, A fp32 in gmem (prefetch kept) ----------------
__global__ __launch_bounds__(256) void gemm_f16(
    const float* __restrict__ A, long lda,
    const __half* __restrict__ B,
    float* __restrict__ C, long ldc, int M) {
    __shared__ __half sA[128][40];
    __shared__ __half sB[64][40];
    const int t = threadIdx.x, lane = t & 31, w = t >> 5;
    const int m0 = blockIdx.x * 128, n0 = blockIdx.y * 64;
    const int wr = (w & 3) * 32, wc = (w >> 2) * 32;
    float acc[2][4][4];
#pragma unroll
    for (int i = 0; i < 2; i++)
#pragma unroll
        for (int j = 0; j < 4; j++)
#pragma unroll
            for (int q = 0; q < 4; q++) acc[i][j][q] = 0.f;

    const int ar = t >> 1, ao = (t & 1) * 16;
    const int br = t >> 2, bo = (t & 3) * 8;
    const int am = m0 + ar;
    const bool aok = (am < M);
    const float* pA = A + (size_t)(aok ? am : 0) * lda + ao;
    const __half* pB = B + (size_t)(n0 + br) * 256 + bo;

    const float4 z = make_float4(0, 0, 0, 0);
    float4 a0 = aok ? *(const float4*)(pA)      : z;
    float4 a1 = aok ? *(const float4*)(pA + 4)  : z;
    float4 a2 = aok ? *(const float4*)(pA + 8)  : z;
    float4 a3 = aok ? *(const float4*)(pA + 12) : z;
    uint4 rb = *(const uint4*)(pB);

    for (int k0 = 0; k0 < 256; k0 += 32) {
        *(uint4*)&sA[ar][ao]     = cvt8_f16(a0, a1);
        *(uint4*)&sA[ar][ao + 8] = cvt8_f16(a2, a3);
        *(uint4*)&sB[br][bo] = rb;
        __syncthreads();
        if (k0 + 32 < 256) {
            const int kn = k0 + 32;
            a0 = aok ? *(const float4*)(pA + kn)      : z;
            a1 = aok ? *(const float4*)(pA + kn + 4)  : z;
            a2 = aok ? *(const float4*)(pA + kn + 8)  : z;
            a3 = aok ? *(const float4*)(pA + kn + 12) : z;
            rb = *(const uint4*)(pB + kn);
        }
#pragma unroll
        for (int kk = 0; kk < 32; kk += 16) {
            uint32_t af[2][4], bf[4][2];
            const int arow = wr + (lane >> 2);
            const int acol = kk + (lane & 3) * 2;
#pragma unroll
            for (int mt = 0; mt < 2; mt++) {
                const int r0 = arow + mt * 16;
                af[mt][0] = *(const uint32_t*)&sA[r0][acol];
                af[mt][1] = *(const uint32_t*)&sA[r0 + 8][acol];
                af[mt][2] = *(const uint32_t*)&sA[r0][acol + 8];
                af[mt][3] = *(const uint32_t*)&sA[r0 + 8][acol + 8];
            }
#pragma unroll
            for (int nt = 0; nt < 4; nt++) {
                const int nr = wc + nt * 8 + (lane >> 2);
                bf[nt][0] = *(const uint32_t*)&sB[nr][acol];
                bf[nt][1] = *(const uint32_t*)&sB[nr][acol + 8];
            }
#pragma unroll
            for (int mt = 0; mt < 2; mt++)
#pragma unroll
                for (int nt = 0; nt < 4; nt++)
                    MMA_F16(acc[mt][nt], af[mt], bf[nt]);
        }
        __syncthreads();
    }
    const int grp = lane >> 2, qc = (lane & 3) * 2;
#pragma unroll
    for (int mt = 0; mt < 2; mt++)
#pragma unroll
        for (int nt = 0; nt < 4; nt++) {
            const int rg = m0 + wr + mt * 16 + grp;
            const int cg = n0 + wc + nt * 8 + qc;
            if (rg < M)
                *(float2*)&C[(size_t)rg * ldc + cg] =
                    make_float2(acc[mt][nt][0], acc[mt][nt][1]);
            if (rg + 8 < M)
                *(float2*)&C[(size_t)(rg + 8) * ldc + cg] =
                    make_float2(acc[mt][nt][2], acc[mt][nt][3]);
        }
}

// ---------------- fp16 GEMM, A fp16 in gmem (final proj) -------------------
__global__ __launch_bounds__(256) void gemm_h16(
    const __half* __restrict__ A,
    const __half* __restrict__ B,
    float* __restrict__ C, int M) {
    __shared__ __half sA[128][40];
    __shared__ __half sB[64][40];
    const int t = threadIdx.x, lane = t & 31, w = t >> 5;
    const int m0 = blockIdx.x * 128, n0 = blockIdx.y * 64;
    const int wr = (w & 3) * 32, wc = (w >> 2) * 32;
    float acc[2][4][4];
#pragma unroll
    for (int i = 0; i < 2; i++)
#pragma unroll
        for (int j = 0; j < 4; j++)
#pragma unroll
            for (int q = 0; q < 4; q++) acc[i][j][q] = 0.f;

    const int ar = t >> 1, ao = (t & 1) * 16;
    const int br = t >> 2, bo = (t & 3) * 8;
    const int am = m0 + ar;
    const bool aok = (am < M);
    const __half* pA = A + (size_t)(aok ? am : 0) * 256 + ao;
    const __half* pB = B + (size_t)(n0 + br) * 256 + bo;

    const uint4 uz = make_uint4(0, 0, 0, 0);
    uint4 ra0 = aok ? *(const uint4*)(pA)     : uz;
    uint4 ra1 = aok ? *(const uint4*)(pA + 8) : uz;
    uint4 rb  = *(const uint4*)(pB);

    for (int k0 = 0; k0 < 256; k0 += 32) {
        *(uint4*)&sA[ar][ao]     = ra0;
        *(uint4*)&sA[ar][ao + 8] = ra1;
        *(uint4*)&sB[br][bo] = rb;
        __syncthreads();
        if (k0 + 32 < 256) {
            const int kn = k0 + 32;
            ra0 = aok ? *(const uint4*)(pA + kn)     : uz;
            ra1 = aok ? *(const uint4*)(pA + kn + 8) : uz;
            rb  = *(const uint4*)(pB + kn);
        }
#pragma unroll
        for (int kk = 0; kk < 32; kk += 16) {
            uint32_t af[2][4], bf[4][2];
            const int arow = wr + (lane >> 2);
            const int acol = kk + (lane & 3) * 2;
#pragma unroll
            for (int mt = 0; mt < 2; mt++) {
                const int r0 = arow + mt * 16;
                af[mt][0] = *(const uint32_t*)&sA[r0][acol];
                af[mt][1] = *(const uint32_t*)&sA[r0 + 8][acol];
                af[mt][2] = *(const uint32_t*)&sA[r0][acol + 8];
                af[mt][3] = *(const uint32_t*)&sA[r0 + 8][acol + 8];
            }
#pragma unroll
            for (int nt = 0; nt < 4; nt++) {
                const int nr = wc + nt * 8 + (lane >> 2);
                bf[nt][0] = *(const uint32_t*)&sB[nr][acol];
                bf[nt][1] = *(const uint32_t*)&sB[nr][acol + 8];
            }
#pragma unroll
            for (int mt = 0; mt < 2; mt++)
#pragma unroll
                for (int nt = 0; nt < 4; nt++)
                    MMA_F16(acc[mt][nt], af[mt], bf[nt]);
        }
        __syncthreads();
    }
    const int grp = lane >> 2, qc = (lane & 3) * 2;
#pragma unroll
    for (int mt = 0; mt < 2; mt++)
#pragma unroll
        for (int nt = 0; nt < 4; nt++) {
            const int rg = m0 + wr + mt * 16 + grp;
            const int cg = n0 + wc + nt * 8 + qc;
            if (rg < M)
                *(float2*)&C[(size_t)rg * 256 + cg] =
                    make_float2(acc[mt][nt][0], acc[mt][nt][1]);
            if (rg + 8 < M)
                *(float2*)&C[(size_t)(rg + 8) * 256 + cg] =
                    make_float2(acc[mt][nt][2], acc[mt][nt][3]);
        }
}

// ---------------- u via tensor cores (3-split bf16), fp16 output ------------
__global__ __launch_bounds__(256) void u_tc(int M) {
    __shared__ __nv_bfloat16 sAh[128][40], sAl[128][40];
    __shared__ __nv_bfloat16 sBh[64][40], sBl[64][40];
    const int t = threadIdx.x, lane = t & 31, w = t >> 5;
    const int m0 = blockIdx.x * 128, i0 = blockIdx.y * 64, h = blockIdx.z;
    const int wr = (w & 3) * 32, wc = (w >> 2) * 32;
    float acc[2][4][4];
#pragma unroll
    for (int i = 0; i < 2; i++)
#pragma unroll
        for (int j = 0; j < 4; j++)
#pragma unroll
            for (int q = 0; q < 4; q++) acc[i][j][q] = 0.f;

    const int ar = t >> 1, ao = (t & 1) * 16;
    const int br = t >> 2, bo = (t & 3) * 8;
    const int am = m0 + ar;
    const bool aok = (am < M);
    {
        float4 z = make_float4(0, 0, 0, 0);
        const float* pA = g_K + (size_t)(aok ? am : 0) * 256 + h * 32 + ao;
        float4 a0 = aok ? *(const float4*)(pA)      : z;
        float4 a1 = aok ? *(const float4*)(pA + 4)  : z;
        float4 a2 = aok ? *(const float4*)(pA + 8)  : z;
        float4 a3 = aok ? *(const float4*)(pA + 12) : z;
        uint4 h0, l0, h1, l1;
        split8(a0, a1, h0, l0);
        split8(a2, a3, h1, l1);
        *(uint4*)&sAh[ar][ao]     = h0;
        *(uint4*)&sAh[ar][ao + 8] = h1;
        *(uint4*)&sAl[ar][ao]     = l0;
        *(uint4*)&sAl[ar][ao + 8] = l1;
        *(uint4*)&sBh[br][bo] = *(const uint4*)&g_WqTh[(size_t)(i0 + br) * 256 + h * 32 + bo];
        *(uint4*)&sBl[br][bo] = *(const uint4*)&g_WqTl[(size_t)(i0 + br) * 256 + h * 32 + bo];
    }
    __syncthreads();
#pragma unroll
    for (int kk = 0; kk < 32; kk += 16) {
        uint32_t afh[2][4], afl[2][4], bfh[4][2], bfl[4][2];
        const int arow = wr + (lane >> 2);
        const int acol = kk + (lane & 3) * 2;
#pragma unroll
        for (int mt = 0; mt < 2; mt++) {
            const int r0 = arow + mt * 16;
            afh[mt][0] = *(const uint32_t*)&sAh[r0][acol];
            afh[mt][1] = *(const uint32_t*)&sAh[r0 + 8][acol];
            afh[mt][2] = *(const uint32_t*)&sAh[r0][acol + 8];
            afh[mt][3] = *(const uint32_t*)&sAh[r0 + 8][acol + 8];
            afl[mt][0] = *(const uint32_t*)&sAl[r0][acol];
            afl[mt][1] = *(const uint32_t*)&sAl[r0 + 8][acol];
            afl[mt][2] = *(const uint32_t*)&sAl[r0][acol + 8];
            afl[mt][3] = *(const uint32_t*)&sAl[r0 + 8][acol + 8];
        }
#pragma unroll
        for (int nt = 0; nt < 4; nt++) {
            const int nr = wc + nt * 8 + (lane >> 2);
            bfh[nt][0] = *(const uint32_t*)&sBh[nr][acol];
            bfh[nt][1] = *(const uint32_t*)&sBh[nr][acol + 8];
            bfl[nt][0] = *(const uint32_t*)&sBl[nr][acol];
            bfl[nt][1] = *(const uint32_t*)&sBl[nr][acol + 8];
        }
#pragma unroll
        for (int mt = 0; mt < 2; mt++)
#pragma unroll
            for (int nt = 0; nt < 4; nt++) {
                MMA_BF16(acc[mt][nt], afh[mt], bfh[nt]);
                MMA_BF16(acc[mt][nt], afh[mt], bfl[nt]);
                MMA_BF16(acc[mt][nt], afl[mt], bfh[nt]);
            }
    }
    const int grp = lane >> 2, qc = (lane & 3) * 2;
#pragma unroll
    for (int mt = 0; mt < 2; mt++)
#pragma unroll
        for (int nt = 0; nt < 4; nt++) {
            const int rg = m0 + wr + mt * 16 + grp;
            const int cg = h * 256 + i0 + wc + nt * 8 + qc;
            if (rg < M) {
                __half2 v = __floats2half2_rn(acc[mt][nt][0], acc[mt][nt][1]);
                *(__half2*)&g_U[(size_t)rg * 2048 + cg] = v;
            }
            if (rg + 8 < M) {
                __half2 v = __floats2half2_rn(acc[mt][nt][2], acc[mt][nt][3]);
                *(__half2*)&g_U[(size_t)(rg + 8) * 2048 + cg] = v;
            }
        }
}

// ---------------- vproj: A fp16 in gmem, fp16 Wv, fp16 V out ---------------
__global__ __launch_bounds__(256) void vproj_f16(int M) {
    __shared__ __half sA[128][40];
    __shared__ __half sB[32][40];
    const int t = threadIdx.x, lane = t & 31, w = t >> 5;
    const int m0 = blockIdx.x * 128, h = blockIdx.y;
    const int wr = (w & 3) * 32, wc = (w >> 2) * 16;
    float acc[2][2][4];
#pragma unroll
    for (int i = 0; i < 2; i++)
#pragma unroll
        for (int j = 0; j < 2; j++)
#pragma unroll
            for (int q = 0; q < 4; q++) acc[i][j][q] = 0.f;

    const int ar = t >> 1, ao = (t & 1) * 16;
    const int br = t >> 3, bo = (t & 7) * 4;
    const int am = m0 + ar;
    const bool aok = (am < M);
    const __half* pA = g_A + (size_t)(aok ? am : 0) * 2048 + h * 256 + ao;
    const __half* pB = g_WvH + (size_t)(h * 32 + br) * 256 + bo;

    const uint4 uz = make_uint4(0, 0, 0, 0);
    uint4 ra0 = aok ? *(const uint4*)(pA)     : uz;
    uint4 ra1 = aok ? *(const uint4*)(pA + 8) : uz;
    uint2 rb  = *(const uint2*)(pB);

    for (int k0 = 0; k0 < 256; k0 += 32) {
        *(uint4*)&sA[ar][ao]     = ra0;
        *(uint4*)&sA[ar][ao + 8] = ra1;
        *(uint2*)&sB[br][bo] = rb;
        __syncthreads();
        if (k0 + 32 < 256) {
            const int kn = k0 + 32;
            ra0 = aok ? *(const uint4*)(pA + kn)     : uz;
            ra1 = aok ? *(const uint4*)(pA + kn + 8) : uz;
            rb  = *(const uint2*)(pB + kn);
        }
#pragma unroll
        for (int kk = 0; kk < 32; kk += 16) {
            uint32_t af[2][4], bf[2][2];
            const int arow = wr + (lane >> 2);
            const int acol = kk + (lane & 3) * 2;
#pragma unroll
            for (int mt = 0; mt < 2; mt++) {
                const int r0 = arow + mt * 16;
                af[mt][0] = *(const uint32_t*)&sA[r0][acol];
                af[mt][1] = *(const uint32_t*)&sA[r0 + 8][acol];
                af[mt][2] = *(const uint32_t*)&sA[r0][acol + 8];
                af[mt][3] = *(const uint32_t*)&sA[r0 + 8][acol + 8];
            }
#pragma unroll
            for (int nt = 0; nt < 2; nt++) {
                const int nr = wc + nt * 8 + (lane >> 2);
                bf[nt][0] = *(const uint32_t*)&sB[nr][acol];
                bf[nt][1] = *(const uint32_t*)&sB[nr][acol + 8];
            }
#pragma unroll
            for (int mt = 0; mt < 2; mt++)
#pragma unroll
                for (int nt = 0; nt < 2; nt++)
                    MMA_F16(acc[mt][nt], af[mt], bf[nt]);
        }
        __syncthreads();
    }
    const int grp = lane >> 2, qc = (lane & 3) * 2;
#pragma unroll
    for (int mt = 0; mt < 2; mt++)
#pragma unroll
        for (int nt = 0; nt < 2; nt++) {
            const int rg = m0 + wr + mt * 16 + grp;
            const int cg = h * 32 + wc + nt * 8 + qc;
            if (rg < M) {
                __half2 v = __floats2half2_rn(acc[mt][nt][0], acc[mt][nt][1]);
                *(__half2*)&g_V[(size_t)rg * 256 + cg] = v;
            }
            if (rg + 8 < M) {
                __half2 v = __floats2half2_rn(acc[mt][nt][2], acc[mt][nt][3]);
                *(__half2*)&g_V[(size_t)(rg + 8) * 256 + cg] = v;
            }
        }
}

// ---------------- attention: warp-per-node, packed f32x2 math ----------------
__global__ __launch_bounds__(128) void attn_fused(
        const float* __restrict__ ccw, const float* __restrict__ cw,
        const void* __restrict__ ccwm, const void* __restrict__ cwm,
        const int* __restrict__ pidx, int N) {
    __shared__ float p_sm[4][8][20];
    const int t = threadIdx.x, lane = t & 31, w = t >> 5;
    const int n = blockIdx.x * 4 + w;
    if (n >= N) return;
    const size_t nb = n;
    const int mode = g_maskMode;
    const int myh = (((lane >> 4) & 1) << 2) | (((lane >> 3) & 1) << 1) | ((lane >> 2) & 1);
    const float NEG = __int_as_float(0xff800000);
    const float SCALE = 0.17677669529663688f;
    const size_t ppar = (size_t)pidx[n] * 512 + 256;

    // u packed: up[h][j] = (u[h][j], u[h][j+4])
    u64 up[8][4];
#pragma unroll
    for (int h = 0; h < 8; h++)
#pragma unroll
        for (int j = 0; j < 4; j++) {
            float lo = __half2float(g_U[nb * 2048 + h * 256 + j * 32 + lane]);
            float hi = __half2float(g_U[nb * 2048 + h * 256 + (j + 4) * 32 + lane]);
            PACK2(up[h][j], lo, hi);
        }

    float sc[18];
#pragma unroll
    for (int s = 0; s < 18; s++) {
        const float* src;
        if (s < 8)       src = ccw + nb * 2048 + (size_t)s * 256;
        else if (s == 8) src = g_SP + nb * 512;
        else if (s == 9) src = g_SP + ppar;
        else             src = cw + nb * 2048 + (size_t)(s - 10) * 256;
        float m[8];
#pragma unroll
        for (int j = 0; j < 8; j++) m[j] = src[j * 32 + lane];
        u64 mp[4];
#pragma unroll
        for (int j = 0; j < 4; j++) PACK2(mp[j], m[j], m[j + 4]);
        float part[8];
#pragma unroll
        for (int h = 0; h < 8; h++) {
            u64 a;
            MUL2(a, mp[0], up[h][0]);
            FMA2(a, mp[1], up[h][1], a);
            FMA2(a, mp[2], up[h][2], a);
            FMA2(a, mp[3], up[h][3], a);
            float lo, hi;
            UNPACK2(lo, hi, a);
            part[h] = lo + hi;
        }
#pragma unroll
        for (int i = 0; i < 4; i++) {
            float a = part[i], b = part[i + 4];
            float send = (lane & 16) ? a : b;
            float recv = __shfl_xor_sync(0xFFFFFFFFu, send, 16);
            part[i] = ((lane & 16) ? b : a) + recv;
        }
#pragma unroll
        for (int i = 0; i < 2; i++) {
            float a = part[i], b = part[i + 2];
            float send = (lane & 8) ? a : b;
            float recv = __shfl_xor_sync(0xFFFFFFFFu, send, 8);
            part[i] = ((lane & 8) ? b : a) + recv;
        }
        {
            float a = part[0], b = part[1];
            float send = (lane & 4) ? a : b;
            float recv = __shfl_xor_sync(0xFFFFFFFFu, send, 4);
            part[0] = ((lane & 4) ? b : a) + recv;
        }
        part[0] += __shfl_xor_sync(0xFFFFFFFFu, part[0], 2);
        part[0] += __shfl_xor_sync(0xFFFFFFFFu, part[0], 1);
        sc[s] = part[0];
    }

    unsigned vb = 3u << 8;
#pragma unroll
    for (int s = 0; s < 8; s++)
        if (mask_at(ccwm, n * 8 + s, mode)) vb |= 1u << s;
#pragma unroll
    for (int s = 0; s < 8; s++)
        if (mask_at(cwm, n * 8 + s, mode)) vb |= 1u << (10 + s);
    float mx = NEG;
#pragma unroll
    for (int s = 0; s < 18; s++)
        if ((vb >> s) & 1) mx = fmaxf(mx, sc[s] * SCALE);
    float sum = 0.f;
    float pr[18];
#pragma unroll
    for (int s = 0; s < 18; s++) {
        float e = ((vb >> s) & 1) ? __expf(sc[s] * SCALE - mx) : 0.f;
        pr[s] = e;
        sum += e;
    }
    const float inv = 1.f / sum;
    if ((lane & 3) == 0) {
#pragma unroll
        for (int s = 0; s < 18; s++) p_sm[w][myh][s] = pr[s] * inv;
    }
    __syncwarp();

    // aggregate with packed fma: acc2[h][j] = (acc[h][j], acc[h][j+4])
    u64 acc2[8][4];
#pragma unroll
    for (int h = 0; h < 8; h++)
#pragma unroll
        for (int j = 0; j < 4; j++) acc2[h][j] = 0ULL;
#pragma unroll
    for (int s = 0; s < 18; s++) {
        const float* src;
        if (s < 8)       src = ccw + nb * 2048 + (size_t)s * 256;
        else if (s == 8) src = g_SP + nb * 512;
        else if (s == 9) src = g_SP + ppar;
        else             src = cw + nb * 2048 + (size_t)(s - 10) * 256;
        float m[8];
#pragma unroll
        for (int j = 0; j < 8; j++) m[j] = src[j * 32 + lane];
        u64 mp[4];
#pragma unroll
        for (int j = 0; j < 4; j++) PACK2(mp[j], m[j], m[j + 4]);
#pragma unroll
        for (int h = 0; h < 8; h++) {
            float ph = p_sm[w][h][s];
            u64 pp;
            PACK2(pp, ph, ph);
#pragma unroll
            for (int j = 0; j < 4; j++)
                FMA2(acc2[h][j], pp, mp[j], acc2[h][j]);
        }
    }
#pragma unroll
    for (int h = 0; h < 8; h++)
#pragma unroll
        for (int j = 0; j < 4; j++) {
            float lo, hi;
            UNPACK2(lo, hi, acc2[h][j]);
            g_A[nb * 2048 + h * 256 + j * 32 + lane] = __float2half_rn(lo);
            g_A[nb * 2048 + h * 256 + (j + 4) * 32 + lane] = __float2half_rn(hi);
        }
}

extern "C" void kernel_launch(void* const* d_in, const int* in_sizes, int n_in,
                              void* d_out, int out_size) {
    const float* X    = (const float*)d_in[0];
    const int*   pidx = (const int*)d_in[1];
    const float* ccw  = (const float*)d_in[2];
    const void*  ccwm = d_in[3];
    const float* cw   = (const float*)d_in[4];
    const void*  cwm  = d_in[5];
    const float* Wself = (const float*)d_in[6];
    const float* Wpar  = (const float*)d_in[7];
    const float* Wq    = (const float*)d_in[8];
    const float* Wk    = (const float*)d_in[9];
    const float* Wv    = (const float*)d_in[10];
    const float* Wfin  = (const float*)d_in[11];
    float* out = (float*)d_out;
    const int N = in_sizes[0] / 256;

    float *pK, *pSP;
    __half *pV;
    __nv_bfloat16 *pWkh, *pWkl;
    __half *pWspH, *pWfinH;
    cudaGetSymbolAddress((void**)&pK, g_K);
    cudaGetSymbolAddress((void**)&pV, g_V);
    cudaGetSymbolAddress((void**)&pSP, g_SP);
    cudaGetSymbolAddress((void**)&pWkh, g_Wkh);
    cudaGetSymbolAddress((void**)&pWkl, g_Wkl);
    cudaGetSymbolAddress((void**)&pWspH, g_WspH);
    cudaGetSymbolAddress((void**)&pWfinH, g_WfinH);

    detect_kernel<<<1, 256>>>((const unsigned char*)ccwm, in_sizes[3]);
    prep_weights<<<dim3(64, 6), 1024>>>(Wself, Wpar, Wfin, Wv, Wk, Wq);

    const int MB = (N + 127) / 128;
    gemm_f16<<<dim3(MB, 8), 256>>>(X, 256, pWspH, pSP, 512, N);        // S|P
    gemm_f32s<<<dim3(MB, 4), 256>>>(ccw, 2048, pWkh, pWkl, pK, N);     // K (score path)
    u_tc<<<dim3(MB, 4, 8), 256>>>(N);                                  // U (score path)
    attn_fused<<<(N + 3) / 4, 128>>>(ccw, cw, ccwm, cwm, pidx, N);
    vproj_f16<<<dim3(MB, 8), 256>>>(N);
    gemm_h16<<<dim3(MB, 4), 256>>>(pV, pWfinH, out, N);                // final
}